// round 6
// baseline (speedup 1.0000x reference)
#include <cuda_runtime.h>
#include <cstdint>

typedef unsigned long long ull;

#define Bc 4
#define Tc 12
#define Nc 128
#define Hc 64
#define Pc 14
#define G4 256
#define WSZ 18432            // 72 m-rows * 256 permuted edge weights

// ---------------- scratch ----------------
__device__ float g_preB[Bc*Nc*Tc*G4];
__device__ float g_preG[Bc*Nc*Tc*G4];
__device__ float g_beta [Bc*Nc*Pc];
__device__ float g_gamma[Bc*Nc*Pc];
__device__ float g_clg  [Bc*Nc*Pc*Nc];     // [(b*128+i)*14+p][j]
__device__ float g_WPb[G4*Hc], g_WPg[G4*Hc];
__device__ float g_WPc[WSZ];               // extended edge weights, permuted

// ---------------- helpers ----------------
__device__ __forceinline__ ull fma2(ull a, ull b, ull c) {
    ull d; asm("fma.rn.f32x2 %0, %1, %2, %3;" : "=l"(d) : "l"(a), "l"(b), "l"(c)); return d;
}
__device__ __forceinline__ float lo32(ull v){ return __int_as_float((int)(unsigned)v); }
__device__ __forceinline__ float hi32(ull v){ return __int_as_float((int)(unsigned)(v>>32)); }
__device__ __forceinline__ float sigf(float x){ return __fdividef(1.0f, 1.0f + __expf(-x)); }
__device__ __forceinline__ float tanhf_(float x){ return __fdividef(2.0f, 1.0f + __expf(-2.0f*x)) - 1.0f; }

// Permuted layout: word idx = m*256 + ch*128 + l*4 + u,
// gate k = (ch*2 + (u>>1))*64 + 2*l + (u&1). Lane l reads words lane*4..+3
// (conflict-free LDS.128): 4 f32x2 pairs = gates (2l,2l+1) of groups i,f,g,o.

// ---------------- kernel 0: permute weights ----------------
// b/g: 64 m-rows (Whh only). c: 72 m-rows = [Whh | cWih_i | cWih_j | cb | 0].
__global__ void permute_whh_kernel(const float* __restrict__ bWhh,
                                   const float* __restrict__ gWhh,
                                   const float* __restrict__ cWhh,
                                   const float* __restrict__ cWih,
                                   const float* __restrict__ cb) {
    int idx = blockIdx.x*256 + threadIdx.x;            // 0..18431
    int m = idx >> 8, rest = idx & 255;
    int ch = rest >> 7, l = (rest >> 2) & 31, u = rest & 3;
    int k = (ch*2 + (u >> 1))*64 + 2*l + (u & 1);
    if (m < 64) {
        g_WPb[idx] = bWhh[k*64 + m];
        g_WPg[idx] = gWhh[k*64 + m];
    }
    float v;
    if      (m < 64) v = cWhh[k*64 + m];
    else if (m < 67) v = cWih[k*6 + (m - 64)];
    else if (m < 70) v = cWih[k*6 + 3 + (m - 67)];
    else if (m == 70) v = cb[k];
    else              v = 0.f;
    g_WPc[idx] = v;
}

// ---------------- kernel 1: node input projections ----------------
__global__ void precompute_kernel(const float* __restrict__ xs,
                                  const float* __restrict__ bWih, const float* __restrict__ bb,
                                  const float* __restrict__ gWih, const float* __restrict__ gb) {
    int nt = blockIdx.x;                 // s*12+t, s=b*128+n
    int k  = threadIdx.x;                // 0..255
    int s = nt / Tc, t = nt % Tc;
    int b = s >> 7, n = s & 127;
    const float* xp = xs + (((size_t)(b*Tc + t)*Nc + n)*3);
    float x0 = xp[0], x1 = xp[1], x2 = xp[2];
    size_t o = (size_t)nt*G4 + k;
    g_preB[o] = bb[k] + bWih[k*3+0]*x0 + bWih[k*3+1]*x1 + bWih[k*3+2]*x2;
    g_preG[o] = gb[k] + gWih[k*3+0]*x0 + gWih[k*3+1]*x1 + gWih[k*3+2]*x2;
}

// ---------------- kernel 2: node LSTMs (1 seq/warp; y=0 beta, y=1 gamma) ------
__global__ void __launch_bounds__(256)
node_lstm_kernel(const float* __restrict__ bfW, const float* __restrict__ bfb,
                 const float* __restrict__ gfW, const float* __restrict__ gfb) {
    extern __shared__ float sm[];
    float*  wTp = sm;                          // 16384 floats
    float4* h4  = (float4*)(sm + 16384);       // [8 warps][32]

    const float* WP; const float* pre; const float* fW; const float* fb; float* outp;
    if (blockIdx.y == 0) { WP = g_WPb; pre = g_preB; fW = bfW; fb = bfb; outp = g_beta; }
    else                 { WP = g_WPg; pre = g_preG; fW = gfW; fb = gfb; outp = g_gamma; }

    for (int idx = threadIdx.x; idx < 16384; idx += 256) wTp[idx] = WP[idx];
    __syncthreads();

    int warp = threadIdx.x >> 5, lane = threadIdx.x & 31;
    int s = blockIdx.x*8 + warp;
    const float* prow = pre + (size_t)s*Tc*G4;
    float4* hrow = h4 + warp*32;

    float c0 = 0.f, c1 = 0.f;
    ull acc[4];
    for (int t = 0; t < Tc; ++t) {
        const float* pt = prow + t*G4;
#pragma unroll
        for (int g = 0; g < 4; ++g) acc[g] = *(const ull*)(pt + g*64 + 2*lane);
        if (t > 0) {
#pragma unroll 4
            for (int mp = 0; mp < 32; ++mp) {
                const float* wr = wTp + (2*mp)*256 + lane*4;
                ulonglong2 wa  = *(const ulonglong2*)(wr);
                ulonglong2 wb  = *(const ulonglong2*)(wr + 128);
                ulonglong2 wa1 = *(const ulonglong2*)(wr + 256);
                ulonglong2 wb1 = *(const ulonglong2*)(wr + 384);
                ulonglong2 hh  = *(const ulonglong2*)(hrow + mp);
                acc[0] = fma2(wa.x,  hh.x, acc[0]);
                acc[1] = fma2(wa.y,  hh.x, acc[1]);
                acc[2] = fma2(wb.x,  hh.x, acc[2]);
                acc[3] = fma2(wb.y,  hh.x, acc[3]);
                acc[0] = fma2(wa1.x, hh.y, acc[0]);
                acc[1] = fma2(wa1.y, hh.y, acc[1]);
                acc[2] = fma2(wb1.x, hh.y, acc[2]);
                acc[3] = fma2(wb1.y, hh.y, acc[3]);
            }
        }
        __syncwarp();
        float i0 = sigf(lo32(acc[0])), i1 = sigf(hi32(acc[0]));
        float f0 = sigf(lo32(acc[1])), f1 = sigf(hi32(acc[1]));
        float q0 = tanhf_(lo32(acc[2])), q1 = tanhf_(hi32(acc[2]));
        float o0 = sigf(lo32(acc[3])), o1 = sigf(hi32(acc[3]));
        c0 = f0*c0 + i0*q0;  c1 = f1*c1 + i1*q1;
        float h0 = o0*tanhf_(c0), h1 = o1*tanhf_(c1);
        hrow[lane] = make_float4(h0, h0, h1, h1);
        __syncwarp();
    }
    if (lane < Pc) {
        const float*  wr = fW + lane*Hc;
        const float2* hv = (const float2*)hrow;
        float a = fb[lane];
#pragma unroll
        for (int m = 0; m < Hc; ++m) a += wr[m]*hv[m].x;
        outp[s*Pc + lane] = sigf(a);
    }
}

// ---------------- kernel 3: edge LSTM, K=72 folded projection ----------------
// smem: 18432 w floats (73728B) + 64 edges * 36 float4 (36864B) = 110592B
#define FMA_MP(mp_) do { \
    const float* wr = wTp + (mp_)*512 + lane4; \
    ulonglong2 wa  = *(const ulonglong2*)(wr); \
    ulonglong2 wb  = *(const ulonglong2*)(wr + 128); \
    ulonglong2 wa1 = *(const ulonglong2*)(wr + 256); \
    ulonglong2 wb1 = *(const ulonglong2*)(wr + 384); \
    _Pragma("unroll") \
    for (int e = 0; e < 8; ++e) { \
        ulonglong2 hh = *(const ulonglong2*)(hbase + e*36 + (mp_)); \
        acc[e][0] = fma2(wa.x,  hh.x, acc[e][0]); \
        acc[e][1] = fma2(wa.y,  hh.x, acc[e][1]); \
        acc[e][2] = fma2(wb.x,  hh.x, acc[e][2]); \
        acc[e][3] = fma2(wb.y,  hh.x, acc[e][3]); \
        acc[e][0] = fma2(wa1.x, hh.y, acc[e][0]); \
        acc[e][1] = fma2(wa1.y, hh.y, acc[e][1]); \
        acc[e][2] = fma2(wb1.x, hh.y, acc[e][2]); \
        acc[e][3] = fma2(wb1.y, hh.y, acc[e][3]); \
    } } while(0)

__global__ void __launch_bounds__(256, 2)
edge_lstm_kernel(const float* __restrict__ xs,
                 const float* __restrict__ cfW, const float* __restrict__ cfb) {
    extern __shared__ float sm[];
    float*  wTp = sm;                          // 18432 floats
    float4* h4  = (float4*)(sm + WSZ);         // [64 edges][36]

    for (int idx = threadIdx.x; idx < WSZ; idx += 256) wTp[idx] = g_WPc[idx];

    int warp = threadIdx.x >> 5, lane = threadIdx.x & 31;
    int lane4 = lane*4;
    int ebase = (blockIdx.x*8 + warp)*8;       // 8 edges: same (b,i), j0..j0+7
    int b  = ebase >> 14;
    int i  = (ebase >> 7) & 127;
    int j0 = ebase & 127;
    float4* hbase = h4 + warp*(8*36);

    // const/bias slot + x_0 slots (slots 0..31 are written at every step's epilogue)
    if (lane < 8) {
        const float* xi = xs + (((size_t)(b*Tc + 0)*Nc + i)*3);
        const float* xj = xs + (((size_t)(b*Tc + 0)*Nc + j0 + lane)*3);
        float4* hr = hbase + lane*36;
        hr[32] = make_float4(xi[0], xi[0], xi[1], xi[1]);
        hr[33] = make_float4(xi[2], xi[2], xj[0], xj[0]);
        hr[34] = make_float4(xj[1], xj[1], xj[2], xj[2]);
        hr[35] = make_float4(1.f, 1.f, 0.f, 0.f);
    }
    __syncthreads();

    float c0[8], c1[8];
#pragma unroll
    for (int e = 0; e < 8; ++e) { c0[e] = 0.f; c1[e] = 0.f; }

    ull acc[8][4];
    for (int t = 0; t < Tc; ++t) {
#pragma unroll
        for (int e = 0; e < 8; ++e) {
            acc[e][0] = 0ull; acc[e][1] = 0ull; acc[e][2] = 0ull; acc[e][3] = 0ull;
        }
        if (t == 0) {
            FMA_MP(32); FMA_MP(33); FMA_MP(34); FMA_MP(35);
        } else {
#pragma unroll 2
            for (int mp = 0; mp < 36; ++mp) FMA_MP(mp);
        }
        __syncwarp();
#pragma unroll
        for (int e = 0; e < 8; ++e) {
            float i0 = sigf(lo32(acc[e][0])), i1 = sigf(hi32(acc[e][0]));
            float f0 = sigf(lo32(acc[e][1])), f1 = sigf(hi32(acc[e][1]));
            float q0 = tanhf_(lo32(acc[e][2])), q1 = tanhf_(hi32(acc[e][2]));
            float o0 = sigf(lo32(acc[e][3])), o1 = sigf(hi32(acc[e][3]));
            c0[e] = f0*c0[e] + i0*q0;
            c1[e] = f1*c1[e] + i1*q1;
            float h0 = o0*tanhf_(c0[e]);
            float h1 = o1*tanhf_(c1[e]);
            hbase[e*36 + lane] = make_float4(h0, h0, h1, h1);
        }
        if (t + 1 < Tc && lane < 8) {
            const float* xi = xs + (((size_t)(b*Tc + (t+1))*Nc + i)*3);
            const float* xj = xs + (((size_t)(b*Tc + (t+1))*Nc + j0 + lane)*3);
            float4* hr = hbase + lane*36;
            hr[32] = make_float4(xi[0], xi[0], xi[1], xi[1]);
            hr[33] = make_float4(xi[2], xi[2], xj[0], xj[0]);
            hr[34] = make_float4(xj[1], xj[1], xj[2], xj[2]);
        }
        __syncwarp();
    }
    // fc + sigmoid per edge
#pragma unroll 1
    for (int e = 0; e < 8; ++e) {
        if (lane < Pc) {
            const float*  wr = cfW + lane*Hc;
            const float2* hv = (const float2*)(hbase + e*36);
            float a = cfb[lane];
#pragma unroll
            for (int m = 0; m < Hc; ++m) a += wr[m]*hv[m].x;
            g_clg[(size_t)(((b*Nc + i)*Pc + lane))*Nc + (j0 + e)] = sigf(a);
        }
    }
}

// ---------------- kernel 4: softmax over j + write epi ----------------
__global__ void softmax_kernel(float* __restrict__ out) {
    int row  = blockIdx.x*4 + (threadIdx.x >> 5);   // (b*128+i)*14+p
    int lane = threadIdx.x & 31;
    const float* src = g_clg + (size_t)row*Nc;
    float v[4]; float s = 0.f;
#pragma unroll
    for (int q = 0; q < 4; ++q) { v[q] = __expf(src[lane + 32*q]); s += v[q]; }
#pragma unroll
    for (int off = 16; off; off >>= 1) s += __shfl_xor_sync(0xffffffffu, s, off);
    float inv = __fdividef(1.0f, s);
    int bi = row / Pc, p = row % Pc;
    int b = bi >> 7, i = bi & 127;
    float* e = out + 7168 + ((size_t)((b*Pc + p)*Nc + i))*130;
    if (lane == 0) { e[0] = g_beta[row]; e[1] = g_gamma[row]; }
#pragma unroll
    for (int q = 0; q < 4; ++q) e[2 + lane + 32*q] = v[q]*inv;
}

// ---------------- kernel 5: SIR scan ----------------
__global__ void sir_kernel(const float* __restrict__ x, float* __restrict__ out) {
    int b = blockIdx.x;
    int i = threadIdx.x;
    __shared__ float Ish[Nc];
    const float* xp = x + (((size_t)(b*Tc + (Tc-1))*Nc) + i)*3;
    float S = xp[0], I = xp[1], R = xp[2];
    Ish[i] = I; __syncthreads();
    for (int p = 0; p < Pc; ++p) {
        const float* e = out + 7168 + ((size_t)((b*Pc + p)*Nc + i))*130;
        float beta = e[0], gamma = e[1];
        float inf = 0.f;
#pragma unroll 4
        for (int j = 0; j < Nc; ++j) inf += e[2 + j]*Ish[j];
        float Ntot = fmaxf(S + I + R, 1e-8f);
        float dS = -beta*S/Ntot*inf;
        float dI = -dS - gamma*I;
        float dR = gamma*I;
        float St = fmaxf(S + dS, 0.f);
        float It = fmaxf(I + dI, 0.f);
        float Rt = fmaxf(R + dR, 0.f);
        float sc = Ntot / fmaxf(St + It + Rt, 1e-8f);
        float Inew = fmaxf(-dS, 0.f);
        St *= sc; It *= sc; Rt *= sc;
        size_t idx = (size_t)(b*Pc + p)*Nc + i;
        out[idx] = It;                                      // o1
        float* o3 = out + 7168 + 931840 + idx*3;            // o3: S,I,R
        o3[0] = St; o3[1] = It; o3[2] = Rt;
        out[7168 + 931840 + 21504 + idx] = Inew;            // o4
        __syncthreads();
        S = St; I = It; R = Rt;
        Ish[i] = I;
        __syncthreads();
    }
}

extern "C" void kernel_launch(void* const* d_in, const int* in_sizes, int n_in,
                              void* d_out, int out_size) {
    const float* x_s  = (const float*)d_in[0];
    const float* x    = (const float*)d_in[1];
    const float* bWih = (const float*)d_in[2];
    const float* bWhh = (const float*)d_in[3];
    const float* bb   = (const float*)d_in[4];
    const float* bfW  = (const float*)d_in[5];
    const float* bfb  = (const float*)d_in[6];
    const float* gWih = (const float*)d_in[7];
    const float* gWhh = (const float*)d_in[8];
    const float* gb   = (const float*)d_in[9];
    const float* gfW  = (const float*)d_in[10];
    const float* gfb  = (const float*)d_in[11];
    const float* cWih = (const float*)d_in[12];
    const float* cWhh = (const float*)d_in[13];
    const float* cb   = (const float*)d_in[14];
    const float* cfW  = (const float*)d_in[15];
    const float* cfb  = (const float*)d_in[16];
    float* out = (float*)d_out;

    static bool attr_done = false;
    if (!attr_done) {
        cudaFuncSetAttribute(node_lstm_kernel, cudaFuncAttributeMaxDynamicSharedMemorySize, 69632);
        cudaFuncSetAttribute(edge_lstm_kernel, cudaFuncAttributeMaxDynamicSharedMemorySize, 110592);
        attr_done = true;
    }

    permute_whh_kernel<<<72, 256>>>(bWhh, gWhh, cWhh, cWih, cb);
    precompute_kernel<<<Bc*Nc*Tc, 256>>>(x_s, bWih, bb, gWih, gb);
    node_lstm_kernel<<<dim3(64, 2), 256, 69632>>>(bfW, bfb, gfW, gfb);
    edge_lstm_kernel<<<1024, 256, 110592>>>(x_s, cfW, cfb);
    softmax_kernel<<<1792, 128>>>(out);
    sir_kernel<<<Bc, Nc>>>(x, out);
}

// round 7
// speedup vs baseline: 2.3962x; 2.3962x over previous
#include <cuda_runtime.h>
#include <cstdint>

typedef unsigned long long ull;

#define Bc 4
#define Tc 12
#define Nc 128
#define Hc 64
#define Pc 14
#define G4 256

// ---------------- scratch ----------------
__device__ float g_preB[Bc*Nc*Tc*G4];
__device__ float g_preG[Bc*Nc*Tc*G4];
__device__ float g_beta [Bc*Nc*Pc];
__device__ float g_gamma[Bc*Nc*Pc];
__device__ float g_clg  [Bc*Nc*Pc*Nc];     // [(b*128+i)*14+p][j]
__device__ float g_WPb[G4*Hc], g_WPg[G4*Hc];
__device__ float g_Wx[G4*76];              // edge ext weights [n][k], tf32 bits, stride 76

// ---------------- helpers ----------------
__device__ __forceinline__ ull fma2(ull a, ull b, ull c) {
    ull d; asm("fma.rn.f32x2 %0, %1, %2, %3;" : "=l"(d) : "l"(a), "l"(b), "l"(c)); return d;
}
__device__ __forceinline__ float lo32(ull v){ return __int_as_float((int)(unsigned)v); }
__device__ __forceinline__ float hi32(ull v){ return __int_as_float((int)(unsigned)(v>>32)); }
__device__ __forceinline__ float sigf(float x){ return __fdividef(1.0f, 1.0f + __expf(-x)); }
__device__ __forceinline__ float tanhf_(float x){ return __fdividef(2.0f, 1.0f + __expf(-2.0f*x)) - 1.0f; }

__device__ __forceinline__ float tf32f(float x){
    uint32_t r; asm("cvt.rna.tf32.f32 %0, %1;" : "=r"(r) : "f"(x));
    return __uint_as_float(r);
}
__device__ __forceinline__ void mma8(float& d0, float& d1, float& d2, float& d3,
                                     uint32_t a0, uint32_t a1, uint32_t a2, uint32_t a3,
                                     uint32_t b0, uint32_t b1){
    asm volatile("mma.sync.aligned.m16n8k8.row.col.f32.tf32.tf32.f32 "
        "{%0,%1,%2,%3}, {%4,%5,%6,%7}, {%8,%9}, {%0,%1,%2,%3};"
        : "+f"(d0), "+f"(d1), "+f"(d2), "+f"(d3)
        : "r"(a0), "r"(a1), "r"(a2), "r"(a3), "r"(b0), "r"(b1));
}

// ---------------- kernel 0a: permute node Whh ----------------
__global__ void permute_whh_kernel(const float* __restrict__ bWhh,
                                   const float* __restrict__ gWhh) {
    int idx = blockIdx.x*256 + threadIdx.x;            // 0..16383
    int m = idx >> 8, rest = idx & 255;
    int ch = rest >> 7, l = (rest >> 2) & 31, u = rest & 3;
    int k = (ch*2 + (u >> 1))*64 + 2*l + (u & 1);
    g_WPb[idx] = bWhh[k*64 + m];
    g_WPg[idx] = gWhh[k*64 + m];
}

// ---------------- kernel 0b: build edge ext weights (tf32) ----------------
// W[n][k]: k<64 Whh; 64..66 cWih_i; 67..69 cWih_j; 70 bias; 71..75 zero
__global__ void prep_wx_kernel(const float* __restrict__ cWhh,
                               const float* __restrict__ cWih,
                               const float* __restrict__ cb) {
    int idx = blockIdx.x*256 + threadIdx.x;            // 0..19455
    int n = idx / 76, k = idx % 76;
    float v;
    if      (k < 64) v = cWhh[n*64 + k];
    else if (k < 67) v = cWih[n*6 + (k - 64)];
    else if (k < 70) v = cWih[n*6 + 3 + (k - 67)];
    else if (k == 70) v = cb[n];
    else              v = 0.f;
    g_Wx[idx] = tf32f(v);
}

// ---------------- kernel 1: node input projections ----------------
__global__ void precompute_kernel(const float* __restrict__ xs,
                                  const float* __restrict__ bWih, const float* __restrict__ bb,
                                  const float* __restrict__ gWih, const float* __restrict__ gb) {
    int nt = blockIdx.x;
    int k  = threadIdx.x;
    int s = nt / Tc, t = nt % Tc;
    int b = s >> 7, n = s & 127;
    const float* xp = xs + (((size_t)(b*Tc + t)*Nc + n)*3);
    float x0 = xp[0], x1 = xp[1], x2 = xp[2];
    size_t o = (size_t)nt*G4 + k;
    g_preB[o] = bb[k] + bWih[k*3+0]*x0 + bWih[k*3+1]*x1 + bWih[k*3+2]*x2;
    g_preG[o] = gb[k] + gWih[k*3+0]*x0 + gWih[k*3+1]*x1 + gWih[k*3+2]*x2;
}

// ---------------- kernel 2: node LSTMs (passing SIMT version) ----------------
__global__ void __launch_bounds__(256)
node_lstm_kernel(const float* __restrict__ bfW, const float* __restrict__ bfb,
                 const float* __restrict__ gfW, const float* __restrict__ gfb) {
    extern __shared__ float sm[];
    float*  wTp = sm;
    float4* h4  = (float4*)(sm + 16384);

    const float* WP; const float* pre; const float* fW; const float* fb; float* outp;
    if (blockIdx.y == 0) { WP = g_WPb; pre = g_preB; fW = bfW; fb = bfb; outp = g_beta; }
    else                 { WP = g_WPg; pre = g_preG; fW = gfW; fb = gfb; outp = g_gamma; }

    for (int idx = threadIdx.x; idx < 16384; idx += 256) wTp[idx] = WP[idx];
    __syncthreads();

    int warp = threadIdx.x >> 5, lane = threadIdx.x & 31;
    int s = blockIdx.x*8 + warp;
    const float* prow = pre + (size_t)s*Tc*G4;
    float4* hrow = h4 + warp*32;

    float c0 = 0.f, c1 = 0.f;
    ull acc[4];
    for (int t = 0; t < Tc; ++t) {
        const float* pt = prow + t*G4;
#pragma unroll
        for (int g = 0; g < 4; ++g) acc[g] = *(const ull*)(pt + g*64 + 2*lane);
        if (t > 0) {
#pragma unroll 4
            for (int mp = 0; mp < 32; ++mp) {
                const float* wr = wTp + (2*mp)*256 + lane*4;
                ulonglong2 wa  = *(const ulonglong2*)(wr);
                ulonglong2 wb  = *(const ulonglong2*)(wr + 128);
                ulonglong2 wa1 = *(const ulonglong2*)(wr + 256);
                ulonglong2 wb1 = *(const ulonglong2*)(wr + 384);
                ulonglong2 hh  = *(const ulonglong2*)(hrow + mp);
                acc[0] = fma2(wa.x,  hh.x, acc[0]);
                acc[1] = fma2(wa.y,  hh.x, acc[1]);
                acc[2] = fma2(wb.x,  hh.x, acc[2]);
                acc[3] = fma2(wb.y,  hh.x, acc[3]);
                acc[0] = fma2(wa1.x, hh.y, acc[0]);
                acc[1] = fma2(wa1.y, hh.y, acc[1]);
                acc[2] = fma2(wb1.x, hh.y, acc[2]);
                acc[3] = fma2(wb1.y, hh.y, acc[3]);
            }
        }
        __syncwarp();
        float i0 = sigf(lo32(acc[0])), i1 = sigf(hi32(acc[0]));
        float f0 = sigf(lo32(acc[1])), f1 = sigf(hi32(acc[1]));
        float q0 = tanhf_(lo32(acc[2])), q1 = tanhf_(hi32(acc[2]));
        float o0 = sigf(lo32(acc[3])), o1 = sigf(hi32(acc[3]));
        c0 = f0*c0 + i0*q0;  c1 = f1*c1 + i1*q1;
        float h0 = o0*tanhf_(c0), h1 = o1*tanhf_(c1);
        hrow[lane] = make_float4(h0, h0, h1, h1);
        __syncwarp();
    }
    if (lane < Pc) {
        const float*  wr = fW + lane*Hc;
        const float2* hv = (const float2*)hrow;
        float a = fb[lane];
#pragma unroll
        for (int m = 0; m < Hc; ++m) a += wr[m]*hv[m].x;
        outp[s*Pc + lane] = sigf(a);
    }
}

// ---------------- kernel 3: edge LSTM via mma.sync tf32 ----------------
// CTA = (b,i,jhalf): 64 edges. A[64x76] smem (h|x_i|x_j|1|0), B[256x76] weights.
// Warp w owns n-cols {g*64 + 8w .. +8} for all 4 gate groups, all 4 m-tiles.
#define SB_F 0
#define SA_F 19456
#define SXI_F 24320
#define SXJ_F 24368
#define SMF_TOT 27440           // floats -> 109760 bytes

__global__ void __launch_bounds__(256, 2)
edge_mma_kernel(const float* __restrict__ xs,
                const float* __restrict__ cfW, const float* __restrict__ cfb) {
    extern __shared__ float sm[];
    float* Bs = sm + SB_F;
    float* As = sm + SA_F;
    float* Xi = sm + SXI_F;
    float* Xj = sm + SXJ_F;
    int tid = threadIdx.x, w = tid >> 5, lane = tid & 31;
    int bx = blockIdx.x;
    int jh = bx & 1, i = (bx >> 1) & 127, b = bx >> 8;
    int j0 = jh*64;

    // copy weights (already tf32 bits)
    {
        const float4* src = (const float4*)g_Wx;
        float4* dst = (float4*)Bs;
        for (int idx = tid; idx < 4864; idx += 256) dst[idx] = src[idx];
    }
    // stage x (tf32)
    if (tid < 36) {
        int t = tid/3, q = tid%3;
        Xi[t*4 + q] = tf32f(xs[(((size_t)(b*Tc + t))*Nc + i)*3 + q]);
    }
    for (int idx = tid; idx < 2304; idx += 256) {
        int t = idx/192, r = idx%192, e = r/3, q = r%3;
        Xj[(t*64 + e)*4 + q] = tf32f(xs[(((size_t)(b*Tc + t))*Nc + j0 + e)*3 + q]);
    }
    __syncthreads();
    // init A cols 64..75 for t=0
    if (tid < 64) {
        int e = tid; float* ar = As + e*76;
        ar[64] = Xi[0]; ar[65] = Xi[1]; ar[66] = Xi[2];
        ar[67] = Xj[e*4+0]; ar[68] = Xj[e*4+1]; ar[69] = Xj[e*4+2];
        ar[70] = 1.0f;
#pragma unroll
        for (int q = 71; q < 76; ++q) ar[q] = 0.f;
    }
    __syncthreads();

    const uint32_t* A32 = (const uint32_t*)As;
    const uint32_t* B32 = (const uint32_t*)Bs;
    int r0 = lane >> 2, c0 = lane & 3;

    float d[4][4][4];
    float cst[16];
#pragma unroll
    for (int q = 0; q < 16; ++q) cst[q] = 0.f;

    for (int t = 0; t < Tc; ++t) {
#pragma unroll
        for (int mt = 0; mt < 4; ++mt)
#pragma unroll
        for (int g = 0; g < 4; ++g)
#pragma unroll
        for (int q = 0; q < 4; ++q) d[mt][g][q] = 0.f;

        int kt0 = (t == 0) ? 8 : 0;
        for (int kt = kt0; kt < 9; ++kt) {
            int cc0 = kt*8 + c0;
            uint32_t a[4][4];
#pragma unroll
            for (int mt = 0; mt < 4; ++mt) {
                int rr = mt*16 + r0;
                a[mt][0] = A32[rr*76 + cc0];
                a[mt][1] = A32[(rr+8)*76 + cc0];
                a[mt][2] = A32[rr*76 + cc0 + 4];
                a[mt][3] = A32[(rr+8)*76 + cc0 + 4];
            }
#pragma unroll
            for (int g = 0; g < 4; ++g) {
                int n0 = g*64 + w*8 + r0;
                uint32_t b0 = B32[n0*76 + cc0];
                uint32_t b1 = B32[n0*76 + cc0 + 4];
#pragma unroll
                for (int mt = 0; mt < 4; ++mt)
                    mma8(d[mt][g][0], d[mt][g][1], d[mt][g][2], d[mt][g][3],
                         a[mt][0], a[mt][1], a[mt][2], a[mt][3], b0, b1);
            }
        }
        __syncthreads();
        bool last = (t == Tc - 1);
#pragma unroll
        for (int mt = 0; mt < 4; ++mt)
#pragma unroll
        for (int rr = 0; rr < 2; ++rr)
#pragma unroll
        for (int cc = 0; cc < 2; ++cc) {
            int di = rr*2 + cc;
            float iv = sigf  (d[mt][0][di]);
            float fv = sigf  (d[mt][1][di]);
            float gv = tanhf_(d[mt][2][di]);
            float ov = sigf  (d[mt][3][di]);
            int ci = mt*4 + rr*2 + cc;
            float cs = fv*cst[ci] + iv*gv;
            cst[ci] = cs;
            float h = ov*tanhf_(cs);
            int edge = mt*16 + r0 + rr*8;
            int k = w*8 + 2*c0 + cc;
            As[edge*76 + k] = last ? h : tf32f(h);
        }
        if (!last && tid < 64) {
            int e = tid; float* ar = As + e*76;
            const float* xi = Xi + (t+1)*4;
            const float* xj = Xj + ((t+1)*64 + e)*4;
            ar[64] = xi[0]; ar[65] = xi[1]; ar[66] = xi[2];
            ar[67] = xj[0]; ar[68] = xj[1]; ar[69] = xj[2];
        }
        __syncthreads();
    }

    // FC: warp w -> edges w*8..w*8+7
    if (lane < Pc) {
#pragma unroll 1
        for (int e8 = 0; e8 < 8; ++e8) {
            int e = w*8 + e8;
            const float* hrow = As + e*76;
            float a = cfb[lane];
#pragma unroll
            for (int k = 0; k < Hc; ++k) a += __ldg(&cfW[lane*Hc + k]) * hrow[k];
            g_clg[((size_t)((b*Nc + i)*Pc + lane))*Nc + (j0 + e)] = sigf(a);
        }
    }
}

// ---------------- kernel 4: softmax over j + write epi ----------------
__global__ void softmax_kernel(float* __restrict__ out) {
    int row  = blockIdx.x*4 + (threadIdx.x >> 5);
    int lane = threadIdx.x & 31;
    const float* src = g_clg + (size_t)row*Nc;
    float v[4]; float s = 0.f;
#pragma unroll
    for (int q = 0; q < 4; ++q) { v[q] = __expf(src[lane + 32*q]); s += v[q]; }
#pragma unroll
    for (int off = 16; off; off >>= 1) s += __shfl_xor_sync(0xffffffffu, s, off);
    float inv = __fdividef(1.0f, s);
    int bi = row / Pc, p = row % Pc;
    int b = bi >> 7, i = bi & 127;
    float* e = out + 7168 + ((size_t)((b*Pc + p)*Nc + i))*130;
    if (lane == 0) { e[0] = g_beta[row]; e[1] = g_gamma[row]; }
#pragma unroll
    for (int q = 0; q < 4; ++q) e[2 + lane + 32*q] = v[q]*inv;
}

// ---------------- kernel 5: SIR scan ----------------
__global__ void sir_kernel(const float* __restrict__ x, float* __restrict__ out) {
    int b = blockIdx.x;
    int i = threadIdx.x;
    __shared__ float Ish[Nc];
    const float* xp = x + (((size_t)(b*Tc + (Tc-1))*Nc) + i)*3;
    float S = xp[0], I = xp[1], R = xp[2];
    Ish[i] = I; __syncthreads();
    for (int p = 0; p < Pc; ++p) {
        const float* e = out + 7168 + ((size_t)((b*Pc + p)*Nc + i))*130;
        float beta = e[0], gamma = e[1];
        float inf = 0.f;
#pragma unroll 4
        for (int j = 0; j < Nc; ++j) inf += e[2 + j]*Ish[j];
        float Ntot = fmaxf(S + I + R, 1e-8f);
        float dS = -beta*S/Ntot*inf;
        float dI = -dS - gamma*I;
        float dR = gamma*I;
        float St = fmaxf(S + dS, 0.f);
        float It = fmaxf(I + dI, 0.f);
        float Rt = fmaxf(R + dR, 0.f);
        float sc = Ntot / fmaxf(St + It + Rt, 1e-8f);
        float Inew = fmaxf(-dS, 0.f);
        St *= sc; It *= sc; Rt *= sc;
        size_t idx = (size_t)(b*Pc + p)*Nc + i;
        out[idx] = It;
        float* o3 = out + 7168 + 931840 + idx*3;
        o3[0] = St; o3[1] = It; o3[2] = Rt;
        out[7168 + 931840 + 21504 + idx] = Inew;
        __syncthreads();
        S = St; I = It; R = Rt;
        Ish[i] = I;
        __syncthreads();
    }
}

extern "C" void kernel_launch(void* const* d_in, const int* in_sizes, int n_in,
                              void* d_out, int out_size) {
    const float* x_s  = (const float*)d_in[0];
    const float* x    = (const float*)d_in[1];
    const float* bWih = (const float*)d_in[2];
    const float* bWhh = (const float*)d_in[3];
    const float* bb   = (const float*)d_in[4];
    const float* bfW  = (const float*)d_in[5];
    const float* bfb  = (const float*)d_in[6];
    const float* gWih = (const float*)d_in[7];
    const float* gWhh = (const float*)d_in[8];
    const float* gb   = (const float*)d_in[9];
    const float* gfW  = (const float*)d_in[10];
    const float* gfb  = (const float*)d_in[11];
    const float* cWih = (const float*)d_in[12];
    const float* cWhh = (const float*)d_in[13];
    const float* cb   = (const float*)d_in[14];
    const float* cfW  = (const float*)d_in[15];
    const float* cfb  = (const float*)d_in[16];
    float* out = (float*)d_out;

    static bool attr_done = false;
    if (!attr_done) {
        cudaFuncSetAttribute(node_lstm_kernel, cudaFuncAttributeMaxDynamicSharedMemorySize, 69632);
        cudaFuncSetAttribute(edge_mma_kernel,  cudaFuncAttributeMaxDynamicSharedMemorySize, SMF_TOT*4);
        attr_done = true;
    }

    permute_whh_kernel<<<64, 256>>>(bWhh, gWhh);
    prep_wx_kernel<<<76, 256>>>(cWhh, cWih, cb);
    precompute_kernel<<<Bc*Nc*Tc, 256>>>(x_s, bWih, bb, gWih, gb);
    node_lstm_kernel<<<dim3(64, 2), 256, 69632>>>(bfW, bfb, gfW, gfb);
    edge_mma_kernel<<<1024, 256, SMF_TOT*4>>>(x_s, cfW, cfb);
    softmax_kernel<<<1792, 128>>>(out);
    sir_kernel<<<Bc, Nc>>>(x, out);
}

// round 8
// speedup vs baseline: 3.0654x; 1.2793x over previous
#include <cuda_runtime.h>
#include <cstdint>

#define Bc 4
#define Tc 12
#define Nc 128
#define Hc 64
#define Pc 14
#define G4 256

// ---------------- scratch ----------------
__device__ float g_beta [Bc*Nc*Pc];
__device__ float g_gamma[Bc*Nc*Pc];
__device__ float g_clg  [Bc*Nc*Pc*Nc];     // [(b*128+i)*14+p][j]
__device__ float g_Wx [G4*76];             // edge ext weights [n][k] tf32, stride 76
__device__ float g_WxB[G4*76];             // node beta ext weights
__device__ float g_WxG[G4*76];             // node gamma ext weights

// ---------------- helpers ----------------
__device__ __forceinline__ float sigf(float x){ return __fdividef(1.0f, 1.0f + __expf(-x)); }
__device__ __forceinline__ float tanhf_(float x){ return __fdividef(2.0f, 1.0f + __expf(-2.0f*x)) - 1.0f; }
__device__ __forceinline__ float tf32f(float x){
    uint32_t r; asm("cvt.rna.tf32.f32 %0, %1;" : "=r"(r) : "f"(x));
    return __uint_as_float(r);
}
__device__ __forceinline__ void mma8(float& d0, float& d1, float& d2, float& d3,
                                     uint32_t a0, uint32_t a1, uint32_t a2, uint32_t a3,
                                     uint32_t b0, uint32_t b1){
    asm volatile("mma.sync.aligned.m16n8k8.row.col.f32.tf32.tf32.f32 "
        "{%0,%1,%2,%3}, {%4,%5,%6,%7}, {%8,%9}, {%0,%1,%2,%3};"
        : "+f"(d0), "+f"(d1), "+f"(d2), "+f"(d3)
        : "r"(a0), "r"(a1), "r"(a2), "r"(a3), "r"(b0), "r"(b1));
}

// ---------------- kernel 0: build all three ext weight tiles (tf32) -----------
// edge: k<64 cWhh; 64..66 cWih_i; 67..69 cWih_j; 70 bias; 71..75 zero
// node: k<64 Whh;  64..66 Wih;    67 bias; 68..75 zero
__global__ void prep_wx_kernel(const float* __restrict__ cWhh, const float* __restrict__ cWih,
                               const float* __restrict__ cb,
                               const float* __restrict__ bWhh, const float* __restrict__ bWih,
                               const float* __restrict__ bb,
                               const float* __restrict__ gWhh, const float* __restrict__ gWih,
                               const float* __restrict__ gb) {
    int idx = blockIdx.x*256 + threadIdx.x;            // 0..19455
    int n = idx / 76, k = idx % 76;
    float ve, vb, vg;
    if      (k < 64) { ve = cWhh[n*64+k]; vb = bWhh[n*64+k]; vg = gWhh[n*64+k]; }
    else if (k < 67) { ve = cWih[n*6+(k-64)]; vb = bWih[n*3+(k-64)]; vg = gWih[n*3+(k-64)]; }
    else if (k == 67){ ve = cWih[n*6+3];      vb = bb[n];            vg = gb[n]; }
    else if (k < 70) { ve = cWih[n*6+3+(k-67)]; vb = 0.f; vg = 0.f; }
    else if (k == 70){ ve = cb[n]; vb = 0.f; vg = 0.f; }
    else             { ve = 0.f;   vb = 0.f; vg = 0.f; }
    g_Wx [idx] = tf32f(ve);
    g_WxB[idx] = tf32f(vb);
    g_WxG[idx] = tf32f(vg);
}

// ---------------- kernel 1: unified LSTM via mma.sync tf32 ----------------
// CTA bx<1024: edge (b,i,jhalf), 64 edges. bx>=1024: node, 16 CTAs (net, blk of 64 seqs).
// A[64x76] smem rows = [h(64) | ext(12)], B[256x76].
// Warp w owns n-cols {g*64 + 8w .. +8} for gate groups g=i,f,g,o, all 4 m-tiles.
#define SB_F 0
#define SA_F 19456
#define SXI_F 24320
#define SXJ_F 24368
#define SMF_TOT 27440           // floats -> 109760 bytes

__global__ void __launch_bounds__(256, 2)
lstm_mma_kernel(const float* __restrict__ xs,
                const float* __restrict__ cfW, const float* __restrict__ cfb,
                const float* __restrict__ bfW, const float* __restrict__ bfb,
                const float* __restrict__ gfW, const float* __restrict__ gfb) {
    extern __shared__ float sm[];
    float* Bs = sm + SB_F;
    float* As = sm + SA_F;
    float* Xi = sm + SXI_F;
    float* Xj = sm + SXJ_F;
    int tid = threadIdx.x, w = tid >> 5, lane = tid & 31;
    int bx = blockIdx.x;
    bool isEdge = bx < 1024;
    int b = 0, i = 0, j0 = 0, blk = 0, net = 0;
    const float* Bg;
    if (isEdge) {
        j0 = (bx & 1)*64; i = (bx >> 1) & 127; b = bx >> 8;
        Bg = g_Wx;
    } else {
        int nb = bx - 1024; net = nb >> 3; blk = nb & 7;
        Bg = net ? g_WxG : g_WxB;
    }

    // copy weights (already tf32 bits)
    {
        const float4* src = (const float4*)Bg;
        float4* dst = (float4*)Bs;
        for (int idx = tid; idx < 4864; idx += 256) dst[idx] = src[idx];
    }
    // stage x
    if (isEdge) {
        if (tid < 36) {
            int t = tid/3, q = tid%3;
            Xi[t*4 + q] = xs[(((size_t)(b*Tc + t))*Nc + i)*3 + q];
        }
        for (int idx = tid; idx < 2304; idx += 256) {
            int t = idx/192, r = idx%192, e = r/3, q = r%3;
            Xj[(t*64 + e)*4 + q] = xs[(((size_t)(b*Tc + t))*Nc + j0 + e)*3 + q];
        }
    } else {
        for (int idx = tid; idx < 2304; idx += 256) {
            int t = idx/192, r = idx%192, e = r/3, q = r%3;
            int s = blk*64 + e, bb_ = s >> 7, nn = s & 127;
            Xj[(t*64 + e)*4 + q] = xs[(((size_t)(bb_*Tc + t))*Nc + nn)*3 + q];
        }
    }
    __syncthreads();
    // init A ext cols for t=0
    if (tid < 64) {
        float* ar = As + tid*76;
#pragma unroll
        for (int q = 64; q < 76; ++q) ar[q] = 0.f;
        if (isEdge) {
            ar[64] = Xi[0]; ar[65] = Xi[1]; ar[66] = Xi[2];
            ar[67] = Xj[tid*4+0]; ar[68] = Xj[tid*4+1]; ar[69] = Xj[tid*4+2];
            ar[70] = 1.0f;
        } else {
            ar[64] = Xj[tid*4+0]; ar[65] = Xj[tid*4+1]; ar[66] = Xj[tid*4+2];
            ar[67] = 1.0f;
        }
    }
    __syncthreads();

    const uint32_t* A32 = (const uint32_t*)As;
    const uint32_t* B32 = (const uint32_t*)Bs;
    int r0 = lane >> 2, c0 = lane & 3;

    float d[4][4][4];
    float cst[16];
#pragma unroll
    for (int q = 0; q < 16; ++q) cst[q] = 0.f;

    for (int t = 0; t < Tc; ++t) {
#pragma unroll
        for (int mt = 0; mt < 4; ++mt)
#pragma unroll
        for (int g = 0; g < 4; ++g)
#pragma unroll
        for (int q = 0; q < 4; ++q) d[mt][g][q] = 0.f;

        if (t) {
#pragma unroll 4
            for (int kt = 0; kt < 8; ++kt) {
                int cc0 = kt*8 + c0;
                uint32_t a[4][4];
#pragma unroll
                for (int mt = 0; mt < 4; ++mt) {
                    int rr = mt*16 + r0;
                    a[mt][0] = A32[rr*76 + cc0];
                    a[mt][1] = A32[(rr+8)*76 + cc0];
                    a[mt][2] = A32[rr*76 + cc0 + 4];
                    a[mt][3] = A32[(rr+8)*76 + cc0 + 4];
                }
#pragma unroll
                for (int g = 0; g < 4; ++g) {
                    int n0 = g*64 + w*8 + r0;
                    uint32_t b0 = B32[n0*76 + cc0];
                    uint32_t b1 = B32[n0*76 + cc0 + 4];
#pragma unroll
                    for (int mt = 0; mt < 4; ++mt)
                        mma8(d[mt][g][0], d[mt][g][1], d[mt][g][2], d[mt][g][3],
                             a[mt][0], a[mt][1], a[mt][2], a[mt][3], b0, b1);
                }
            }
        }
        {   // kt = 8 (ext cols), always
            int cc0 = 64 + c0;
            uint32_t a[4][4];
#pragma unroll
            for (int mt = 0; mt < 4; ++mt) {
                int rr = mt*16 + r0;
                a[mt][0] = A32[rr*76 + cc0];
                a[mt][1] = A32[(rr+8)*76 + cc0];
                a[mt][2] = A32[rr*76 + cc0 + 4];
                a[mt][3] = A32[(rr+8)*76 + cc0 + 4];
            }
#pragma unroll
            for (int g = 0; g < 4; ++g) {
                int n0 = g*64 + w*8 + r0;
                uint32_t b0 = B32[n0*76 + cc0];
                uint32_t b1 = B32[n0*76 + cc0 + 4];
#pragma unroll
                for (int mt = 0; mt < 4; ++mt)
                    mma8(d[mt][g][0], d[mt][g][1], d[mt][g][2], d[mt][g][3],
                         a[mt][0], a[mt][1], a[mt][2], a[mt][3], b0, b1);
            }
        }
        __syncthreads();
        bool last = (t == Tc - 1);
#pragma unroll
        for (int mt = 0; mt < 4; ++mt)
#pragma unroll
        for (int rr = 0; rr < 2; ++rr)
#pragma unroll
        for (int cc = 0; cc < 2; ++cc) {
            int di = rr*2 + cc;
            float iv = sigf  (d[mt][0][di]);
            float fv = sigf  (d[mt][1][di]);
            float gv = tanhf_(d[mt][2][di]);
            float ov = sigf  (d[mt][3][di]);
            int ci = mt*4 + rr*2 + cc;
            float cs = fv*cst[ci] + iv*gv;
            cst[ci] = cs;
            float h = ov*tanhf_(cs);
            int edge = mt*16 + r0 + rr*8;
            int k = w*8 + 2*c0 + cc;
            As[edge*76 + k] = last ? h : tf32f(h);
        }
        if (!last && tid < 64) {
            float* ar = As + tid*76;
            if (isEdge) {
                const float* xi = Xi + (t+1)*4;
                const float* xj = Xj + ((t+1)*64 + tid)*4;
                ar[64] = xi[0]; ar[65] = xi[1]; ar[66] = xi[2];
                ar[67] = xj[0]; ar[68] = xj[1]; ar[69] = xj[2];
            } else {
                const float* xj = Xj + ((t+1)*64 + tid)*4;
                ar[64] = xj[0]; ar[65] = xj[1]; ar[66] = xj[2];
            }
        }
        __syncthreads();
    }

    // FC + sigmoid: warp w -> rows w*8..w*8+7
    const float* fW = isEdge ? cfW : (net ? gfW : bfW);
    const float* fb = isEdge ? cfb : (net ? gfb : bfb);
    if (lane < Pc) {
        float a[8];
#pragma unroll
        for (int e = 0; e < 8; ++e) a[e] = fb[lane];
        for (int k = 0; k < Hc; ++k) {
            float wk = __ldg(&fW[lane*Hc + k]);
#pragma unroll
            for (int e = 0; e < 8; ++e) a[e] += wk * As[(w*8 + e)*76 + k];
        }
#pragma unroll
        for (int e = 0; e < 8; ++e) {
            float v = sigf(a[e]);
            int row = w*8 + e;
            if (isEdge) {
                g_clg[((size_t)((b*Nc + i)*Pc + lane))*Nc + (j0 + row)] = v;
            } else {
                int s = blk*64 + row;
                (net ? g_gamma : g_beta)[s*Pc + lane] = v;
            }
        }
    }
}

// ---------------- kernel 2: softmax over j + write epi ----------------
__global__ void softmax_kernel(float* __restrict__ out) {
    int row  = blockIdx.x*4 + (threadIdx.x >> 5);
    int lane = threadIdx.x & 31;
    const float* src = g_clg + (size_t)row*Nc;
    float v[4]; float s = 0.f;
#pragma unroll
    for (int q = 0; q < 4; ++q) { v[q] = __expf(src[lane + 32*q]); s += v[q]; }
#pragma unroll
    for (int off = 16; off; off >>= 1) s += __shfl_xor_sync(0xffffffffu, s, off);
    float inv = __fdividef(1.0f, s);
    int bi = row / Pc, p = row % Pc;
    int b = bi >> 7, i = bi & 127;
    float* e = out + 7168 + ((size_t)((b*Pc + p)*Nc + i))*130;
    if (lane == 0) { e[0] = g_beta[row]; e[1] = g_gamma[row]; }
#pragma unroll
    for (int q = 0; q < 4; ++q) e[2 + lane + 32*q] = v[q]*inv;
}

// ---------------- kernel 3: SIR scan (coalesced, 4 thr/row) ----------------
// smem: Ctile[128][132] + Ish[128] = 17024 floats = 68096 B
__global__ void sir_kernel(const float* __restrict__ x, float* __restrict__ out) {
    extern __shared__ float sms[];
    float* Ct  = sms;              // stride 132
    float* Ish = sms + 128*132;
    int b = blockIdx.x;
    int tid = threadIdx.x;         // 0..511
    int i = tid >> 2, q = tid & 3;

    float S = 0.f, I = 0.f, R = 0.f;
    if (q == 0) {
        const float* xp = x + (((size_t)(b*Tc + (Tc-1))*Nc) + i)*3;
        S = xp[0]; I = xp[1]; R = xp[2];
        Ish[i] = I;
    }
    __syncthreads();

    for (int p = 0; p < Pc; ++p) {
        const float* ep = out + 7168 + ((size_t)((b*Pc + p)*Nc))*130;
        // load c tile: 128 rows x 64 float2 (c starts at +2, 8B aligned)
        for (int idx = tid; idx < 8192; idx += 512) {
            int row = idx >> 6, c2 = idx & 63;
            float2 v = *(const float2*)(ep + row*130 + 2 + c2*2);
            *(float2*)(Ct + row*132 + c2*2) = v;
        }
        __syncthreads();
        float acc = 0.f;
        const float* cr = Ct + i*132 + q*32;
        const float* Iq = Ish + q*32;
#pragma unroll 8
        for (int jj = 0; jj < 32; ++jj) acc += cr[jj]*Iq[jj];
        acc += __shfl_xor_sync(0xffffffffu, acc, 1);
        acc += __shfl_xor_sync(0xffffffffu, acc, 2);
        __syncthreads();
        if (q == 0) {
            const float* e0 = ep + (size_t)i*130;
            float beta = e0[0], gamma = e0[1];
            float Ntot = fmaxf(S + I + R, 1e-8f);
            float dS = -beta*S/Ntot*acc;
            float dI = -dS - gamma*I;
            float dR = gamma*I;
            float St = fmaxf(S + dS, 0.f);
            float It = fmaxf(I + dI, 0.f);
            float Rt = fmaxf(R + dR, 0.f);
            float sc = Ntot / fmaxf(St + It + Rt, 1e-8f);
            float Inew = fmaxf(-dS, 0.f);
            St *= sc; It *= sc; Rt *= sc;
            size_t idx = (size_t)(b*Pc + p)*Nc + i;
            out[idx] = It;                                      // o1
            float* o3 = out + 7168 + 931840 + idx*3;            // o3: S,I,R
            o3[0] = St; o3[1] = It; o3[2] = Rt;
            out[7168 + 931840 + 21504 + idx] = Inew;            // o4
            S = St; I = It; R = Rt;
            Ish[i] = I;
        }
        __syncthreads();
    }
}

extern "C" void kernel_launch(void* const* d_in, const int* in_sizes, int n_in,
                              void* d_out, int out_size) {
    const float* x_s  = (const float*)d_in[0];
    const float* x    = (const float*)d_in[1];
    const float* bWih = (const float*)d_in[2];
    const float* bWhh = (const float*)d_in[3];
    const float* bb   = (const float*)d_in[4];
    const float* bfW  = (const float*)d_in[5];
    const float* bfb  = (const float*)d_in[6];
    const float* gWih = (const float*)d_in[7];
    const float* gWhh = (const float*)d_in[8];
    const float* gb   = (const float*)d_in[9];
    const float* gfW  = (const float*)d_in[10];
    const float* gfb  = (const float*)d_in[11];
    const float* cWih = (const float*)d_in[12];
    const float* cWhh = (const float*)d_in[13];
    const float* cb   = (const float*)d_in[14];
    const float* cfW  = (const float*)d_in[15];
    const float* cfb  = (const float*)d_in[16];
    float* out = (float*)d_out;

    static bool attr_done = false;
    if (!attr_done) {
        cudaFuncSetAttribute(lstm_mma_kernel, cudaFuncAttributeMaxDynamicSharedMemorySize, SMF_TOT*4);
        cudaFuncSetAttribute(sir_kernel,      cudaFuncAttributeMaxDynamicSharedMemorySize, 68096);
        attr_done = true;
    }

    prep_wx_kernel<<<76, 256>>>(cWhh, cWih, cb, bWhh, bWih, bb, gWhh, gWih, gb);
    lstm_mma_kernel<<<1040, 256, SMF_TOT*4>>>(x_s, cfW, cfb, bfW, bfb, gfW, gfb);
    softmax_kernel<<<1792, 128>>>(out);
    sir_kernel<<<Bc, 512, 68096>>>(x, out);
}

// round 9
// speedup vs baseline: 3.3227x; 1.0839x over previous
#include <cuda_runtime.h>
#include <cstdint>

#define Bc 4
#define Tc 12
#define Nc 128
#define Hc 64
#define Pc 14
#define G4 256

// ---------------- scratch ----------------
__device__ float g_beta [Bc*Nc*Pc];
__device__ float g_gamma[Bc*Nc*Pc];
__device__ float g_clg  [Bc*Nc*Pc*Nc];     // [(b*128+i)*14+p][j]
__device__ float g_cs   [Bc*Pc*Nc*Nc];     // [(b*14+p)*128+i][j] softmaxed, dense
__device__ float g_Wx [G4*76];
__device__ float g_WxB[G4*76];
__device__ float g_WxG[G4*76];

// ---------------- helpers ----------------
__device__ __forceinline__ float sigf(float x){ return __fdividef(1.0f, 1.0f + __expf(-x)); }
__device__ __forceinline__ float tanhf_(float x){ return __fdividef(2.0f, 1.0f + __expf(-2.0f*x)) - 1.0f; }
__device__ __forceinline__ float tf32f(float x){
    uint32_t r; asm("cvt.rna.tf32.f32 %0, %1;" : "=r"(r) : "f"(x));
    return __uint_as_float(r);
}
__device__ __forceinline__ void mma8(float& d0, float& d1, float& d2, float& d3,
                                     uint32_t a0, uint32_t a1, uint32_t a2, uint32_t a3,
                                     uint32_t b0, uint32_t b1){
    asm volatile("mma.sync.aligned.m16n8k8.row.col.f32.tf32.tf32.f32 "
        "{%0,%1,%2,%3}, {%4,%5,%6,%7}, {%8,%9}, {%0,%1,%2,%3};"
        : "+f"(d0), "+f"(d1), "+f"(d2), "+f"(d3)
        : "r"(a0), "r"(a1), "r"(a2), "r"(a3), "r"(b0), "r"(b1));
}
__device__ __forceinline__ uint32_t smem_u32(const void* p){
    uint32_t a; asm("{ .reg .u64 t; cvta.to.shared.u64 t, %1; cvt.u32.u64 %0, t; }" : "=r"(a) : "l"(p));
    return a;
}

// ---------------- kernel 0: build ext weight tiles (tf32) ----------------
__global__ void prep_wx_kernel(const float* __restrict__ cWhh, const float* __restrict__ cWih,
                               const float* __restrict__ cb,
                               const float* __restrict__ bWhh, const float* __restrict__ bWih,
                               const float* __restrict__ bb,
                               const float* __restrict__ gWhh, const float* __restrict__ gWih,
                               const float* __restrict__ gb) {
    int idx = blockIdx.x*256 + threadIdx.x;
    int n = idx / 76, k = idx % 76;
    float ve, vb, vg;
    if      (k < 64) { ve = cWhh[n*64+k]; vb = bWhh[n*64+k]; vg = gWhh[n*64+k]; }
    else if (k < 67) { ve = cWih[n*6+(k-64)]; vb = bWih[n*3+(k-64)]; vg = gWih[n*3+(k-64)]; }
    else if (k == 67){ ve = cWih[n*6+3];      vb = bb[n];            vg = gb[n]; }
    else if (k < 70) { ve = cWih[n*6+3+(k-67)]; vb = 0.f; vg = 0.f; }
    else if (k == 70){ ve = cb[n]; vb = 0.f; vg = 0.f; }
    else             { ve = 0.f;   vb = 0.f; vg = 0.f; }
    g_Wx [idx] = tf32f(ve);
    g_WxB[idx] = tf32f(vb);
    g_WxG[idx] = tf32f(vg);
}

// ---------------- kernel 1: unified LSTM via mma.sync tf32 (unchanged) --------
#define SB_F 0
#define SA_F 19456
#define SXI_F 24320
#define SXJ_F 24368
#define SMF_TOT 27440

__global__ void __launch_bounds__(256, 2)
lstm_mma_kernel(const float* __restrict__ xs,
                const float* __restrict__ cfW, const float* __restrict__ cfb,
                const float* __restrict__ bfW, const float* __restrict__ bfb,
                const float* __restrict__ gfW, const float* __restrict__ gfb) {
    extern __shared__ float sm[];
    float* Bs = sm + SB_F;
    float* As = sm + SA_F;
    float* Xi = sm + SXI_F;
    float* Xj = sm + SXJ_F;
    int tid = threadIdx.x, w = tid >> 5, lane = tid & 31;
    int bx = blockIdx.x;
    bool isEdge = bx < 1024;
    int b = 0, i = 0, j0 = 0, blk = 0, net = 0;
    const float* Bg;
    if (isEdge) {
        j0 = (bx & 1)*64; i = (bx >> 1) & 127; b = bx >> 8;
        Bg = g_Wx;
    } else {
        int nb = bx - 1024; net = nb >> 3; blk = nb & 7;
        Bg = net ? g_WxG : g_WxB;
    }

    {
        const float4* src = (const float4*)Bg;
        float4* dst = (float4*)Bs;
        for (int idx = tid; idx < 4864; idx += 256) dst[idx] = src[idx];
    }
    if (isEdge) {
        if (tid < 36) {
            int t = tid/3, q = tid%3;
            Xi[t*4 + q] = xs[(((size_t)(b*Tc + t))*Nc + i)*3 + q];
        }
        for (int idx = tid; idx < 2304; idx += 256) {
            int t = idx/192, r = idx%192, e = r/3, q = r%3;
            Xj[(t*64 + e)*4 + q] = xs[(((size_t)(b*Tc + t))*Nc + j0 + e)*3 + q];
        }
    } else {
        for (int idx = tid; idx < 2304; idx += 256) {
            int t = idx/192, r = idx%192, e = r/3, q = r%3;
            int s = blk*64 + e, bb_ = s >> 7, nn = s & 127;
            Xj[(t*64 + e)*4 + q] = xs[(((size_t)(bb_*Tc + t))*Nc + nn)*3 + q];
        }
    }
    __syncthreads();
    if (tid < 64) {
        float* ar = As + tid*76;
#pragma unroll
        for (int q = 64; q < 76; ++q) ar[q] = 0.f;
        if (isEdge) {
            ar[64] = Xi[0]; ar[65] = Xi[1]; ar[66] = Xi[2];
            ar[67] = Xj[tid*4+0]; ar[68] = Xj[tid*4+1]; ar[69] = Xj[tid*4+2];
            ar[70] = 1.0f;
        } else {
            ar[64] = Xj[tid*4+0]; ar[65] = Xj[tid*4+1]; ar[66] = Xj[tid*4+2];
            ar[67] = 1.0f;
        }
    }
    __syncthreads();

    const uint32_t* A32 = (const uint32_t*)As;
    const uint32_t* B32 = (const uint32_t*)Bs;
    int r0 = lane >> 2, c0 = lane & 3;

    float d[4][4][4];
    float cst[16];
#pragma unroll
    for (int q = 0; q < 16; ++q) cst[q] = 0.f;

    for (int t = 0; t < Tc; ++t) {
#pragma unroll
        for (int mt = 0; mt < 4; ++mt)
#pragma unroll
        for (int g = 0; g < 4; ++g)
#pragma unroll
        for (int q = 0; q < 4; ++q) d[mt][g][q] = 0.f;

        if (t) {
#pragma unroll 4
            for (int kt = 0; kt < 8; ++kt) {
                int cc0 = kt*8 + c0;
                uint32_t a[4][4];
#pragma unroll
                for (int mt = 0; mt < 4; ++mt) {
                    int rr = mt*16 + r0;
                    a[mt][0] = A32[rr*76 + cc0];
                    a[mt][1] = A32[(rr+8)*76 + cc0];
                    a[mt][2] = A32[rr*76 + cc0 + 4];
                    a[mt][3] = A32[(rr+8)*76 + cc0 + 4];
                }
#pragma unroll
                for (int g = 0; g < 4; ++g) {
                    int n0 = g*64 + w*8 + r0;
                    uint32_t b0 = B32[n0*76 + cc0];
                    uint32_t b1 = B32[n0*76 + cc0 + 4];
#pragma unroll
                    for (int mt = 0; mt < 4; ++mt)
                        mma8(d[mt][g][0], d[mt][g][1], d[mt][g][2], d[mt][g][3],
                             a[mt][0], a[mt][1], a[mt][2], a[mt][3], b0, b1);
                }
            }
        }
        {
            int cc0 = 64 + c0;
            uint32_t a[4][4];
#pragma unroll
            for (int mt = 0; mt < 4; ++mt) {
                int rr = mt*16 + r0;
                a[mt][0] = A32[rr*76 + cc0];
                a[mt][1] = A32[(rr+8)*76 + cc0];
                a[mt][2] = A32[rr*76 + cc0 + 4];
                a[mt][3] = A32[(rr+8)*76 + cc0 + 4];
            }
#pragma unroll
            for (int g = 0; g < 4; ++g) {
                int n0 = g*64 + w*8 + r0;
                uint32_t b0 = B32[n0*76 + cc0];
                uint32_t b1 = B32[n0*76 + cc0 + 4];
#pragma unroll
                for (int mt = 0; mt < 4; ++mt)
                    mma8(d[mt][g][0], d[mt][g][1], d[mt][g][2], d[mt][g][3],
                         a[mt][0], a[mt][1], a[mt][2], a[mt][3], b0, b1);
            }
        }
        __syncthreads();
        bool last = (t == Tc - 1);
#pragma unroll
        for (int mt = 0; mt < 4; ++mt)
#pragma unroll
        for (int rr = 0; rr < 2; ++rr)
#pragma unroll
        for (int cc = 0; cc < 2; ++cc) {
            int di = rr*2 + cc;
            float iv = sigf  (d[mt][0][di]);
            float fv = sigf  (d[mt][1][di]);
            float gv = tanhf_(d[mt][2][di]);
            float ov = sigf  (d[mt][3][di]);
            int ci = mt*4 + rr*2 + cc;
            float cs = fv*cst[ci] + iv*gv;
            cst[ci] = cs;
            float h = ov*tanhf_(cs);
            int edge = mt*16 + r0 + rr*8;
            int k = w*8 + 2*c0 + cc;
            As[edge*76 + k] = last ? h : tf32f(h);
        }
        if (!last && tid < 64) {
            float* ar = As + tid*76;
            if (isEdge) {
                const float* xi = Xi + (t+1)*4;
                const float* xj = Xj + ((t+1)*64 + tid)*4;
                ar[64] = xi[0]; ar[65] = xi[1]; ar[66] = xi[2];
                ar[67] = xj[0]; ar[68] = xj[1]; ar[69] = xj[2];
            } else {
                const float* xj = Xj + ((t+1)*64 + tid)*4;
                ar[64] = xj[0]; ar[65] = xj[1]; ar[66] = xj[2];
            }
        }
        __syncthreads();
    }

    const float* fW = isEdge ? cfW : (net ? gfW : bfW);
    const float* fb = isEdge ? cfb : (net ? gfb : bfb);
    if (lane < Pc) {
        float a[8];
#pragma unroll
        for (int e = 0; e < 8; ++e) a[e] = fb[lane];
        for (int k = 0; k < Hc; ++k) {
            float wk = __ldg(&fW[lane*Hc + k]);
#pragma unroll
            for (int e = 0; e < 8; ++e) a[e] += wk * As[(w*8 + e)*76 + k];
        }
#pragma unroll
        for (int e = 0; e < 8; ++e) {
            float v = sigf(a[e]);
            int row = w*8 + e;
            if (isEdge) {
                g_clg[((size_t)((b*Nc + i)*Pc + lane))*Nc + (j0 + row)] = v;
            } else {
                int s = blk*64 + row;
                (net ? g_gamma : g_beta)[s*Pc + lane] = v;
            }
        }
    }
}

// ---------------- kernel 2: softmax over j + write epi + dense cs -------------
__global__ void softmax_kernel(float* __restrict__ out) {
    int row  = blockIdx.x*4 + (threadIdx.x >> 5);   // (b*128+i)*14+p
    int lane = threadIdx.x & 31;
    const float* src = g_clg + (size_t)row*Nc;
    float v[4]; float s = 0.f;
#pragma unroll
    for (int q = 0; q < 4; ++q) { v[q] = __expf(src[lane + 32*q]); s += v[q]; }
#pragma unroll
    for (int off = 16; off; off >>= 1) s += __shfl_xor_sync(0xffffffffu, s, off);
    float inv = __fdividef(1.0f, s);
    int bi = row / Pc, p = row % Pc;
    int b = bi >> 7, i = bi & 127;
    float* e = out + 7168 + ((size_t)((b*Pc + p)*Nc + i))*130;
    float* cs = g_cs + ((size_t)((b*Pc + p)*Nc + i))*Nc;
    if (lane == 0) { e[0] = g_beta[row]; e[1] = g_gamma[row]; }
#pragma unroll
    for (int q = 0; q < 4; ++q) {
        float nv = v[q]*inv;
        e[2 + lane + 32*q]  = nv;
        cs[lane + 32*q]     = nv;
    }
}

// ---------------- kernel 3: SIR scan, double-buffered cp.async ----------------
// 1024 threads, 8 per row. smem: 2 tiles [128][136] + Ish[128].
#define SIR_STR 136
#define SIR_TILE (Nc*SIR_STR)                 // 17408 floats
#define SIR_SMEM ((2*SIR_TILE + Nc)*4)        // 139776 bytes

__global__ void __launch_bounds__(1024, 1)
sir_kernel(const float* __restrict__ x, float* __restrict__ out) {
    extern __shared__ float sms[];
    float* buf0 = sms;
    float* buf1 = sms + SIR_TILE;
    float* Ish  = sms + 2*SIR_TILE;
    int b = blockIdx.x;
    int tid = threadIdx.x;                    // 0..1023
    int i = tid >> 3, q = tid & 7;

    float S = 0.f, I = 0.f, R = 0.f;
    if (q == 0) {
        const float* xp = x + (((size_t)(b*Tc + (Tc-1))*Nc) + i)*3;
        S = xp[0]; I = xp[1]; R = xp[2];
        Ish[i] = I;
    }

    const float* csb = g_cs + (size_t)b*Pc*Nc*Nc;
    // prefetch tile 0
    {
        uint32_t dst = smem_u32(buf0);
        const float* src = csb;
        for (int k = 0; k < 4; ++k) {
            int idx = tid + k*1024;           // 0..4095 quads
            int r = idx >> 5, c = idx & 31;
            uint32_t d = dst + (r*SIR_STR + c*4)*4;
            const float* s = src + r*Nc + c*4;
            asm volatile("cp.async.ca.shared.global [%0], [%1], 16;" :: "r"(d), "l"(s));
        }
        asm volatile("cp.async.commit_group;");
    }

    for (int p = 0; p < Pc; ++p) {
        if (p + 1 < Pc) {
            uint32_t dst = smem_u32((p & 1) ? buf0 : buf1);
            const float* src = csb + (size_t)(p+1)*Nc*Nc;
            for (int k = 0; k < 4; ++k) {
                int idx = tid + k*1024;
                int r = idx >> 5, c = idx & 31;
                uint32_t d = dst + (r*SIR_STR + c*4)*4;
                const float* s = src + r*Nc + c*4;
                asm volatile("cp.async.ca.shared.global [%0], [%1], 16;" :: "r"(d), "l"(s));
            }
            asm volatile("cp.async.commit_group;");
            asm volatile("cp.async.wait_group 1;");
        } else {
            asm volatile("cp.async.wait_group 0;");
        }
        __syncthreads();

        const float* Ct = (p & 1) ? buf1 : buf0;
        float acc = 0.f;
        const float* cr = Ct + i*SIR_STR + q*16;
        const float* Iq = Ish + q*16;
#pragma unroll
        for (int jj = 0; jj < 16; ++jj) acc += cr[jj]*Iq[jj];
        acc += __shfl_xor_sync(0xffffffffu, acc, 1);
        acc += __shfl_xor_sync(0xffffffffu, acc, 2);
        acc += __shfl_xor_sync(0xffffffffu, acc, 4);
        __syncthreads();
        if (q == 0) {
            int row = (b*Nc + i)*Pc + p;
            float beta = g_beta[row], gamma = g_gamma[row];
            float Ntot = fmaxf(S + I + R, 1e-8f);
            float dS = -beta*S/Ntot*acc;
            float dI = -dS - gamma*I;
            float dR = gamma*I;
            float St = fmaxf(S + dS, 0.f);
            float It = fmaxf(I + dI, 0.f);
            float Rt = fmaxf(R + dR, 0.f);
            float sc = Ntot / fmaxf(St + It + Rt, 1e-8f);
            float Inew = fmaxf(-dS, 0.f);
            St *= sc; It *= sc; Rt *= sc;
            size_t idx = (size_t)(b*Pc + p)*Nc + i;
            out[idx] = It;                                      // o1
            float* o3 = out + 7168 + 931840 + idx*3;            // o3
            o3[0] = St; o3[1] = It; o3[2] = Rt;
            out[7168 + 931840 + 21504 + idx] = Inew;            // o4
            S = St; I = It; R = Rt;
            Ish[i] = I;
        }
        __syncthreads();
    }
}

extern "C" void kernel_launch(void* const* d_in, const int* in_sizes, int n_in,
                              void* d_out, int out_size) {
    const float* x_s  = (const float*)d_in[0];
    const float* x    = (const float*)d_in[1];
    const float* bWih = (const float*)d_in[2];
    const float* bWhh = (const float*)d_in[3];
    const float* bb   = (const float*)d_in[4];
    const float* bfW  = (const float*)d_in[5];
    const float* bfb  = (const float*)d_in[6];
    const float* gWih = (const float*)d_in[7];
    const float* gWhh = (const float*)d_in[8];
    const float* gb   = (const float*)d_in[9];
    const float* gfW  = (const float*)d_in[10];
    const float* gfb  = (const float*)d_in[11];
    const float* cWih = (const float*)d_in[12];
    const float* cWhh = (const float*)d_in[13];
    const float* cb   = (const float*)d_in[14];
    const float* cfW  = (const float*)d_in[15];
    const float* cfb  = (const float*)d_in[16];
    float* out = (float*)d_out;

    static bool attr_done = false;
    if (!attr_done) {
        cudaFuncSetAttribute(lstm_mma_kernel, cudaFuncAttributeMaxDynamicSharedMemorySize, SMF_TOT*4);
        cudaFuncSetAttribute(sir_kernel,      cudaFuncAttributeMaxDynamicSharedMemorySize, SIR_SMEM);
        attr_done = true;
    }

    prep_wx_kernel<<<76, 256>>>(cWhh, cWih, cb, bWhh, bWih, bb, gWhh, gWih, gb);
    lstm_mma_kernel<<<1040, 256, SMF_TOT*4>>>(x_s, cfW, cfb, bfW, bfb, gfW, gfb);
    softmax_kernel<<<1792, 128>>>(out);
    sir_kernel<<<Bc, 1024, SIR_SMEM>>>(x, out);
}

// round 10
// speedup vs baseline: 3.7438x; 1.1268x over previous
#include <cuda_runtime.h>
#include <cstdint>

#define Bc 4
#define Tc 12
#define Nc 128
#define Hc 64
#define Pc 14
#define G4 256

// ---------------- scratch ----------------
__device__ float g_beta [Bc*Nc*Pc];
__device__ float g_gamma[Bc*Nc*Pc];
__device__ float g_clg  [Bc*Nc*Pc*Nc];     // [(b*128+i)*14+p][j]
__device__ float g_cs   [Bc*Pc*Nc*Nc];     // [(b*14+p)*128+i][j] softmaxed, dense
__device__ float g_Wx [G4*76];
__device__ float g_WxB[G4*76];
__device__ float g_WxG[G4*76];

// ---------------- helpers ----------------
__device__ __forceinline__ float sigf(float x){ return __fdividef(1.0f, 1.0f + __expf(-x)); }
__device__ __forceinline__ float tanha(float x){
    float r; asm("tanh.approx.f32 %0, %1;" : "=f"(r) : "f"(x)); return r;
}
__device__ __forceinline__ float sig2(float x){ return fmaf(tanha(0.5f*x), 0.5f, 0.5f); }
__device__ __forceinline__ float tf32f(float x){
    uint32_t r; asm("cvt.rna.tf32.f32 %0, %1;" : "=r"(r) : "f"(x));
    return __uint_as_float(r);
}
__device__ __forceinline__ void mma8(float& d0, float& d1, float& d2, float& d3,
                                     uint32_t a0, uint32_t a1, uint32_t a2, uint32_t a3,
                                     uint32_t b0, uint32_t b1){
    asm volatile("mma.sync.aligned.m16n8k8.row.col.f32.tf32.tf32.f32 "
        "{%0,%1,%2,%3}, {%4,%5,%6,%7}, {%8,%9}, {%0,%1,%2,%3};"
        : "+f"(d0), "+f"(d1), "+f"(d2), "+f"(d3)
        : "r"(a0), "r"(a1), "r"(a2), "r"(a3), "r"(b0), "r"(b1));
}
__device__ __forceinline__ uint32_t smem_u32(const void* p){
    uint32_t a; asm("{ .reg .u64 t; cvta.to.shared.u64 t, %1; cvt.u32.u64 %0, t; }" : "=r"(a) : "l"(p));
    return a;
}

// ---------------- kernel 0: build ext weight tiles (tf32) ----------------
__global__ void prep_wx_kernel(const float* __restrict__ cWhh, const float* __restrict__ cWih,
                               const float* __restrict__ cb,
                               const float* __restrict__ bWhh, const float* __restrict__ bWih,
                               const float* __restrict__ bb,
                               const float* __restrict__ gWhh, const float* __restrict__ gWih,
                               const float* __restrict__ gb) {
    int idx = blockIdx.x*256 + threadIdx.x;
    int n = idx / 76, k = idx % 76;
    float ve, vb, vg;
    if      (k < 64) { ve = cWhh[n*64+k]; vb = bWhh[n*64+k]; vg = gWhh[n*64+k]; }
    else if (k < 67) { ve = cWih[n*6+(k-64)]; vb = bWih[n*3+(k-64)]; vg = gWih[n*3+(k-64)]; }
    else if (k == 67){ ve = cWih[n*6+3];      vb = bb[n];            vg = gb[n]; }
    else if (k < 70) { ve = cWih[n*6+3+(k-67)]; vb = 0.f; vg = 0.f; }
    else if (k == 70){ ve = cb[n]; vb = 0.f; vg = 0.f; }
    else             { ve = 0.f;   vb = 0.f; vg = 0.f; }
    g_Wx [idx] = tf32f(ve);
    g_WxB[idx] = tf32f(vb);
    g_WxG[idx] = tf32f(vg);
}

// ---------------- kernel 1: unified LSTM via mma.sync tf32 ----------------
#define SB_F 0
#define SA_F 19456
#define SXI_F 24320
#define SXJ_F 24368
#define SMF_TOT 27440

__global__ void __launch_bounds__(256, 2)
lstm_mma_kernel(const float* __restrict__ xs,
                const float* __restrict__ cfW, const float* __restrict__ cfb,
                const float* __restrict__ bfW, const float* __restrict__ bfb,
                const float* __restrict__ gfW, const float* __restrict__ gfb) {
    extern __shared__ float sm[];
    float* Bs = sm + SB_F;
    float* As = sm + SA_F;
    float* Xi = sm + SXI_F;
    float* Xj = sm + SXJ_F;
    int tid = threadIdx.x, w = tid >> 5, lane = tid & 31;
    int bx = blockIdx.x;
    bool isEdge = bx < 1024;
    int b = 0, i = 0, j0 = 0, blk = 0, net = 0;
    const float* Bg;
    if (isEdge) {
        j0 = (bx & 1)*64; i = (bx >> 1) & 127; b = bx >> 8;
        Bg = g_Wx;
    } else {
        int nb = bx - 1024; net = nb >> 3; blk = nb & 7;
        Bg = net ? g_WxG : g_WxB;
    }

    {
        const float4* src = (const float4*)Bg;
        float4* dst = (float4*)Bs;
        for (int idx = tid; idx < 4864; idx += 256) dst[idx] = src[idx];
    }
    if (isEdge) {
        if (tid < 36) {
            int t = tid/3, q = tid%3;
            Xi[t*4 + q] = xs[(((size_t)(b*Tc + t))*Nc + i)*3 + q];
        }
        for (int idx = tid; idx < 2304; idx += 256) {
            int t = idx/192, r = idx%192, e = r/3, q = r%3;
            Xj[(t*64 + e)*4 + q] = xs[(((size_t)(b*Tc + t))*Nc + j0 + e)*3 + q];
        }
    } else {
        for (int idx = tid; idx < 2304; idx += 256) {
            int t = idx/192, r = idx%192, e = r/3, q = r%3;
            int s = blk*64 + e, bb_ = s >> 7, nn = s & 127;
            Xj[(t*64 + e)*4 + q] = xs[(((size_t)(bb_*Tc + t))*Nc + nn)*3 + q];
        }
    }
    __syncthreads();
    if (tid < 64) {
        float* ar = As + tid*76;
#pragma unroll
        for (int q = 64; q < 76; ++q) ar[q] = 0.f;
        if (isEdge) {
            ar[64] = Xi[0]; ar[65] = Xi[1]; ar[66] = Xi[2];
            ar[67] = Xj[tid*4+0]; ar[68] = Xj[tid*4+1]; ar[69] = Xj[tid*4+2];
            ar[70] = 1.0f;
        } else {
            ar[64] = Xj[tid*4+0]; ar[65] = Xj[tid*4+1]; ar[66] = Xj[tid*4+2];
            ar[67] = 1.0f;
        }
    }
    __syncthreads();

    const uint32_t* A32 = (const uint32_t*)As;
    const uint32_t* B32 = (const uint32_t*)Bs;
    int r0 = lane >> 2, c0 = lane & 3;

    float d[4][4][4];
    float cst[16];
#pragma unroll
    for (int q = 0; q < 16; ++q) cst[q] = 0.f;

    for (int t = 0; t < Tc; ++t) {
#pragma unroll
        for (int mt = 0; mt < 4; ++mt)
#pragma unroll
        for (int g = 0; g < 4; ++g)
#pragma unroll
        for (int q = 0; q < 4; ++q) d[mt][g][q] = 0.f;

        if (t) {
#pragma unroll 4
            for (int kt = 0; kt < 8; ++kt) {
                int cc0 = kt*8 + c0;
                uint32_t a[4][4];
#pragma unroll
                for (int mt = 0; mt < 4; ++mt) {
                    int rr = mt*16 + r0;
                    a[mt][0] = A32[rr*76 + cc0];
                    a[mt][1] = A32[(rr+8)*76 + cc0];
                    a[mt][2] = A32[rr*76 + cc0 + 4];
                    a[mt][3] = A32[(rr+8)*76 + cc0 + 4];
                }
#pragma unroll
                for (int g = 0; g < 4; ++g) {
                    int n0 = g*64 + w*8 + r0;
                    uint32_t b0 = B32[n0*76 + cc0];
                    uint32_t b1 = B32[n0*76 + cc0 + 4];
#pragma unroll
                    for (int mt = 0; mt < 4; ++mt)
                        mma8(d[mt][g][0], d[mt][g][1], d[mt][g][2], d[mt][g][3],
                             a[mt][0], a[mt][1], a[mt][2], a[mt][3], b0, b1);
                }
            }
        }
        {
            int cc0 = 64 + c0;
            uint32_t a[4][4];
#pragma unroll
            for (int mt = 0; mt < 4; ++mt) {
                int rr = mt*16 + r0;
                a[mt][0] = A32[rr*76 + cc0];
                a[mt][1] = A32[(rr+8)*76 + cc0];
                a[mt][2] = A32[rr*76 + cc0 + 4];
                a[mt][3] = A32[(rr+8)*76 + cc0 + 4];
            }
#pragma unroll
            for (int g = 0; g < 4; ++g) {
                int n0 = g*64 + w*8 + r0;
                uint32_t b0 = B32[n0*76 + cc0];
                uint32_t b1 = B32[n0*76 + cc0 + 4];
#pragma unroll
                for (int mt = 0; mt < 4; ++mt)
                    mma8(d[mt][g][0], d[mt][g][1], d[mt][g][2], d[mt][g][3],
                         a[mt][0], a[mt][1], a[mt][2], a[mt][3], b0, b1);
            }
        }
        __syncthreads();
        bool last = (t == Tc - 1);
#pragma unroll
        for (int mt = 0; mt < 4; ++mt)
#pragma unroll
        for (int rr = 0; rr < 2; ++rr)
#pragma unroll
        for (int cc = 0; cc < 2; ++cc) {
            int di = rr*2 + cc;
            float iv = sig2 (d[mt][0][di]);
            float fv = sig2 (d[mt][1][di]);
            float gv = tanha(d[mt][2][di]);
            float ov = sig2 (d[mt][3][di]);
            int ci = mt*4 + rr*2 + cc;
            float cs = fv*cst[ci] + iv*gv;
            cst[ci] = cs;
            float h = ov*tanha(cs);
            int edge = mt*16 + r0 + rr*8;
            int k = w*8 + 2*c0 + cc;
            As[edge*76 + k] = last ? h : tf32f(h);
        }
        if (!last && tid < 64) {
            float* ar = As + tid*76;
            if (isEdge) {
                const float* xi = Xi + (t+1)*4;
                const float* xj = Xj + ((t+1)*64 + tid)*4;
                ar[64] = xi[0]; ar[65] = xi[1]; ar[66] = xi[2];
                ar[67] = xj[0]; ar[68] = xj[1]; ar[69] = xj[2];
            } else {
                const float* xj = Xj + ((t+1)*64 + tid)*4;
                ar[64] = xj[0]; ar[65] = xj[1]; ar[66] = xj[2];
            }
        }
        __syncthreads();
    }

    const float* fW = isEdge ? cfW : (net ? gfW : bfW);
    const float* fb = isEdge ? cfb : (net ? gfb : bfb);
    if (lane < Pc) {
        float a[8];
#pragma unroll
        for (int e = 0; e < 8; ++e) a[e] = fb[lane];
        for (int k = 0; k < Hc; ++k) {
            float wk = __ldg(&fW[lane*Hc + k]);
#pragma unroll
            for (int e = 0; e < 8; ++e) a[e] += wk * As[(w*8 + e)*76 + k];
        }
#pragma unroll
        for (int e = 0; e < 8; ++e) {
            float v = sigf(a[e]);
            int row = w*8 + e;
            if (isEdge) {
                g_clg[((size_t)((b*Nc + i)*Pc + lane))*Nc + (j0 + row)] = v;
            } else {
                int s = blk*64 + row;
                (net ? g_gamma : g_beta)[s*Pc + lane] = v;
            }
        }
    }
}

// ---------------- kernel 2: softmax over j + write epi + dense cs -------------
__global__ void softmax_kernel(float* __restrict__ out) {
    int row  = blockIdx.x*4 + (threadIdx.x >> 5);
    int lane = threadIdx.x & 31;
    const float* src = g_clg + (size_t)row*Nc;
    float v[4]; float s = 0.f;
#pragma unroll
    for (int q = 0; q < 4; ++q) { v[q] = __expf(src[lane + 32*q]); s += v[q]; }
#pragma unroll
    for (int off = 16; off; off >>= 1) s += __shfl_xor_sync(0xffffffffu, s, off);
    float inv = __fdividef(1.0f, s);
    int bi = row / Pc, p = row % Pc;
    int b = bi >> 7, i = bi & 127;
    float* e = out + 7168 + ((size_t)((b*Pc + p)*Nc + i))*130;
    float* cs = g_cs + ((size_t)((b*Pc + p)*Nc + i))*Nc;
    if (lane == 0) { e[0] = g_beta[row]; e[1] = g_gamma[row]; }
#pragma unroll
    for (int q = 0; q < 4; ++q) {
        float nv = v[q]*inv;
        e[2 + lane + 32*q]  = nv;
        cs[lane + 32*q]     = nv;
    }
}

// ---------------- kernel 3: SIR scan, triple-buffered cp.async ----------------
// smem: 3 tiles [128][136] + Ish[2][128] + beta/gamma [2][1792]
#define SIR_STR 136
#define SIR_TILE (Nc*SIR_STR)                        // 17408 floats
#define SIR_SMEM ((3*SIR_TILE + 256 + 2*1792)*4)     // 224256 bytes

__global__ void __launch_bounds__(1024, 1)
sir_kernel(const float* __restrict__ x, float* __restrict__ out) {
    extern __shared__ float sms[];
    float* Ish = sms + 3*SIR_TILE;      // [2][128]
    float* Bgs = Ish + 256;             // beta[1792], gamma[1792]
    int b = blockIdx.x;
    int tid = threadIdx.x;
    int i = tid >> 3, q = tid & 7;

    // stage beta/gamma (coalesced)
    for (int idx = tid; idx < 1792; idx += 1024) {
        Bgs[idx]        = g_beta [b*1792 + idx];
        Bgs[1792 + idx] = g_gamma[b*1792 + idx];
    }
    float S = 0.f, I = 0.f, R = 0.f;
    if (q == 0) {
        const float* xp = x + (((size_t)(b*Tc + (Tc-1))*Nc) + i)*3;
        S = xp[0]; I = xp[1]; R = xp[2];
        Ish[i] = I;
    }

    const float* csb = g_cs + (size_t)b*Pc*Nc*Nc;
    int pr = tid >> 5, pc = tid & 31;   // prefetch row/col quads (32 rows per pass)
    auto prefetch = [&](int p){
        uint32_t dst = smem_u32(sms + (p % 3)*SIR_TILE);
        const float* src = csb + (size_t)p*Nc*Nc;
#pragma unroll
        for (int k = 0; k < 4; ++k) {
            int r = pr + k*32;
            uint32_t d = dst + (r*SIR_STR + pc*4)*4;
            const float* s = src + r*Nc + pc*4;
            asm volatile("cp.async.ca.shared.global [%0], [%1], 16;" :: "r"(d), "l"(s));
        }
        asm volatile("cp.async.commit_group;");
    };
    prefetch(0); prefetch(1); prefetch(2);

    for (int p = 0; p < Pc; ++p) {
        asm volatile("cp.async.wait_group 2;");
        __syncthreads();

        const float* Ct = sms + (p % 3)*SIR_TILE;
        const float* Icur = Ish + (p & 1)*128;
        float acc = 0.f;
        const float* cr = Ct + i*SIR_STR + q*16;
        const float* Iq = Icur + q*16;
#pragma unroll
        for (int jj = 0; jj < 16; ++jj) acc += cr[jj]*Iq[jj];
        acc += __shfl_xor_sync(0xffffffffu, acc, 1);
        acc += __shfl_xor_sync(0xffffffffu, acc, 2);
        acc += __shfl_xor_sync(0xffffffffu, acc, 4);
        if (q == 0) {
            float beta = Bgs[i*Pc + p], gamma = Bgs[1792 + i*Pc + p];
            float Ntot = fmaxf(S + I + R, 1e-8f);
            float dS = -beta*S/Ntot*acc;
            float dI = -dS - gamma*I;
            float dR = gamma*I;
            float St = fmaxf(S + dS, 0.f);
            float It = fmaxf(I + dI, 0.f);
            float Rt = fmaxf(R + dR, 0.f);
            float sc = Ntot / fmaxf(St + It + Rt, 1e-8f);
            float Inew = fmaxf(-dS, 0.f);
            St *= sc; It *= sc; Rt *= sc;
            size_t idx = (size_t)(b*Pc + p)*Nc + i;
            out[idx] = It;                                      // o1
            float* o3 = out + 7168 + 931840 + idx*3;            // o3
            o3[0] = St; o3[1] = It; o3[2] = Rt;
            out[7168 + 931840 + 21504 + idx] = Inew;            // o4
            S = St; I = It; R = Rt;
            Ish[((p + 1) & 1)*128 + i] = I;
        }
        __syncthreads();
        if (p + 3 < Pc) prefetch(p + 3);
        else asm volatile("cp.async.commit_group;");
    }
}

extern "C" void kernel_launch(void* const* d_in, const int* in_sizes, int n_in,
                              void* d_out, int out_size) {
    const float* x_s  = (const float*)d_in[0];
    const float* x    = (const float*)d_in[1];
    const float* bWih = (const float*)d_in[2];
    const float* bWhh = (const float*)d_in[3];
    const float* bb   = (const float*)d_in[4];
    const float* bfW  = (const float*)d_in[5];
    const float* bfb  = (const float*)d_in[6];
    const float* gWih = (const float*)d_in[7];
    const float* gWhh = (const float*)d_in[8];
    const float* gb   = (const float*)d_in[9];
    const float* gfW  = (const float*)d_in[10];
    const float* gfb  = (const float*)d_in[11];
    const float* cWih = (const float*)d_in[12];
    const float* cWhh = (const float*)d_in[13];
    const float* cb   = (const float*)d_in[14];
    const float* cfW  = (const float*)d_in[15];
    const float* cfb  = (const float*)d_in[16];
    float* out = (float*)d_out;

    static bool attr_done = false;
    if (!attr_done) {
        cudaFuncSetAttribute(lstm_mma_kernel, cudaFuncAttributeMaxDynamicSharedMemorySize, SMF_TOT*4);
        cudaFuncSetAttribute(sir_kernel,      cudaFuncAttributeMaxDynamicSharedMemorySize, SIR_SMEM);
        attr_done = true;
    }

    prep_wx_kernel<<<76, 256>>>(cWhh, cWih, cb, bWhh, bWih, bb, gWhh, gWih, gb);
    lstm_mma_kernel<<<1040, 256, SMF_TOT*4>>>(x_s, cfW, cfb, bfW, bfb, gfW, gfb);
    softmax_kernel<<<1792, 128>>>(out);
    sir_kernel<<<Bc, 1024, SIR_SMEM>>>(x, out);
}

// round 11
// speedup vs baseline: 4.7288x; 1.2631x over previous
#include <cuda_runtime.h>
#include <cstdint>

#define Bc 4
#define Tc 12
#define Nc 128
#define Hc 64
#define Pc 14
#define G4 256
#define WSTR 44            // words (bf16x2) per row, padded for bank-conflict-free frags

// ---------------- scratch ----------------
__device__ float g_beta [Bc*Nc*Pc];
__device__ float g_gamma[Bc*Nc*Pc];
__device__ float g_clg  [Bc*Nc*Pc*Nc];     // [(b*128+i)*14+p][j]
__device__ float g_cs   [Bc*Pc*Nc*Nc];     // [(b*14+p)*128+i][j] softmaxed, dense
__device__ uint32_t g_Wx [G4*WSTR];        // packed bf16x2 ext weights [n][word]
__device__ uint32_t g_WxB[G4*WSTR];
__device__ uint32_t g_WxG[G4*WSTR];

// ---------------- helpers ----------------
__device__ __forceinline__ float sigf(float x){ return __fdividef(1.0f, 1.0f + __expf(-x)); }
__device__ __forceinline__ float tanha(float x){
    float r; asm("tanh.approx.f32 %0, %1;" : "=f"(r) : "f"(x)); return r;
}
__device__ __forceinline__ float sig2(float x){ return fmaf(tanha(0.5f*x), 0.5f, 0.5f); }
__device__ __forceinline__ uint32_t pk(float lo, float hi){
    uint32_t r; asm("cvt.rn.bf16x2.f32 %0, %1, %2;" : "=r"(r) : "f"(hi), "f"(lo)); return r;
}
__device__ __forceinline__ float bflo(uint32_t w){ return __uint_as_float(w << 16); }
__device__ __forceinline__ float bfhi(uint32_t w){ return __uint_as_float(w & 0xffff0000u); }
__device__ __forceinline__ void mma16(float& d0, float& d1, float& d2, float& d3,
                                      uint32_t a0, uint32_t a1, uint32_t a2, uint32_t a3,
                                      uint32_t b0, uint32_t b1){
    asm volatile("mma.sync.aligned.m16n8k16.row.col.f32.bf16.bf16.f32 "
        "{%0,%1,%2,%3}, {%4,%5,%6,%7}, {%8,%9}, {%0,%1,%2,%3};"
        : "+f"(d0), "+f"(d1), "+f"(d2), "+f"(d3)
        : "r"(a0), "r"(a1), "r"(a2), "r"(a3), "r"(b0), "r"(b1));
}

// ---------------- kernel 0: build ext weight tiles (packed bf16x2) ------------
// edge k-map: k<64 cWhh; 64..66 cWih_i; 67..69 cWih_j; 70 bias; else 0
// node k-map: k<64 Whh;  64..66 Wih;    67 bias; else 0
__device__ __forceinline__ float valE(int n, int k, const float* cWhh, const float* cWih, const float* cb){
    if (k < 64) return cWhh[n*64 + k];
    if (k < 67) return cWih[n*6 + (k - 64)];
    if (k < 70) return cWih[n*6 + 3 + (k - 67)];
    if (k == 70) return cb[n];
    return 0.f;
}
__device__ __forceinline__ float valN(int n, int k, const float* Whh, const float* Wih, const float* bb){
    if (k < 64) return Whh[n*64 + k];
    if (k < 67) return Wih[n*3 + (k - 64)];
    if (k == 67) return bb[n];
    return 0.f;
}
__global__ void prep_wx_kernel(const float* __restrict__ cWhh, const float* __restrict__ cWih,
                               const float* __restrict__ cb,
                               const float* __restrict__ bWhh, const float* __restrict__ bWih,
                               const float* __restrict__ bb,
                               const float* __restrict__ gWhh, const float* __restrict__ gWih,
                               const float* __restrict__ gb) {
    int idx = blockIdx.x*256 + threadIdx.x;       // 0..11263
    if (idx >= G4*WSTR) return;
    int n = idx / WSTR, wi = idx % WSTR;
    int k0 = 2*wi, k1 = 2*wi + 1;
    g_Wx [idx] = pk(valE(n, k0, cWhh, cWih, cb), valE(n, k1, cWhh, cWih, cb));
    g_WxB[idx] = pk(valN(n, k0, bWhh, bWih, bb), valN(n, k1, bWhh, bWih, bb));
    g_WxG[idx] = pk(valN(n, k0, gWhh, gWih, gb), valN(n, k1, gWhh, gWih, gb));
}

// ---------------- kernel 1: unified LSTM via mma.sync bf16 ----------------
// smem words: B[256*44]=11264, A[64*44]=2816, Xi[48], Xj[3072] -> 17200 f = 68800 B
#define SW_B 0
#define SW_A 11264
#define SF_XI 14080
#define SF_XJ 14128
#define SMF_TOT 17200

__global__ void __launch_bounds__(256, 2)
lstm_mma_kernel(const float* __restrict__ xs,
                const float* __restrict__ cfW, const float* __restrict__ cfb,
                const float* __restrict__ bfW, const float* __restrict__ bfb,
                const float* __restrict__ gfW, const float* __restrict__ gfb) {
    extern __shared__ float sm[];
    uint32_t* BW = (uint32_t*)sm + SW_B;
    uint32_t* AW = (uint32_t*)sm + SW_A;
    float* Xi = sm + SF_XI;
    float* Xj = sm + SF_XJ;
    int tid = threadIdx.x, w = tid >> 5, lane = tid & 31;
    int bx = blockIdx.x;
    bool isEdge = bx < 1024;
    int b = 0, i = 0, j0 = 0, blk = 0, net = 0;
    const uint32_t* Bg;
    if (isEdge) {
        j0 = (bx & 1)*64; i = (bx >> 1) & 127; b = bx >> 8;
        Bg = g_Wx;
    } else {
        int nb = bx - 1024; net = nb >> 3; blk = nb & 7;
        Bg = net ? g_WxG : g_WxB;
    }

    {   // copy weights (packed)
        const uint4* src = (const uint4*)Bg;
        uint4* dst = (uint4*)BW;
        for (int idx = tid; idx < 2816; idx += 256) dst[idx] = src[idx];
    }
    // stage x (f32)
    if (isEdge) {
        if (tid < 36) {
            int t = tid/3, q = tid%3;
            Xi[t*4 + q] = xs[(((size_t)(b*Tc + t))*Nc + i)*3 + q];
        }
        for (int idx = tid; idx < 2304; idx += 256) {
            int t = idx/192, r = idx%192, e = r/3, q = r%3;
            Xj[(t*64 + e)*4 + q] = xs[(((size_t)(b*Tc + t))*Nc + j0 + e)*3 + q];
        }
    } else {
        for (int idx = tid; idx < 2304; idx += 256) {
            int t = idx/192, r = idx%192, e = r/3, q = r%3;
            int s = blk*64 + e, bb_ = s >> 7, nn = s & 127;
            Xj[(t*64 + e)*4 + q] = xs[(((size_t)(bb_*Tc + t))*Nc + nn)*3 + q];
        }
    }
    __syncthreads();
    // init A ext words for t=0 (words 32..43)
    if (tid < 64) {
        uint32_t* ar = AW + tid*WSTR;
#pragma unroll
        for (int q = 34; q < WSTR; ++q) ar[q] = 0u;
        if (isEdge) {
            const float* xj = Xj + tid*4;
            ar[32] = pk(Xi[0], Xi[1]);
            ar[33] = pk(Xi[2], xj[0]);
            ar[34] = pk(xj[1], xj[2]);
            ar[35] = pk(1.0f, 0.f);
        } else {
            const float* xj = Xj + tid*4;
            ar[32] = pk(xj[0], xj[1]);
            ar[33] = pk(xj[2], 1.0f);
        }
    }
    __syncthreads();

    int r0 = lane >> 2, c0 = lane & 3;

    float d[4][4][4];
    float cst[16];
#pragma unroll
    for (int q = 0; q < 16; ++q) cst[q] = 0.f;

    for (int t = 0; t < Tc; ++t) {
#pragma unroll
        for (int mt = 0; mt < 4; ++mt)
#pragma unroll
        for (int g = 0; g < 4; ++g)
#pragma unroll
        for (int q = 0; q < 4; ++q) d[mt][g][q] = 0.f;

        for (int kt = (t ? 0 : 4); kt < 5; ++kt) {
            int base = kt*8 + c0;
            uint32_t a[4][4];
#pragma unroll
            for (int mt = 0; mt < 4; ++mt) {
                int rr = mt*16 + r0;
                a[mt][0] = AW[rr*WSTR + base];
                a[mt][1] = AW[(rr+8)*WSTR + base];
                a[mt][2] = AW[rr*WSTR + base + 4];
                a[mt][3] = AW[(rr+8)*WSTR + base + 4];
            }
#pragma unroll
            for (int g = 0; g < 4; ++g) {
                int n0 = g*64 + w*8 + r0;
                uint32_t b0 = BW[n0*WSTR + base];
                uint32_t b1 = BW[n0*WSTR + base + 4];
#pragma unroll
                for (int mt = 0; mt < 4; ++mt)
                    mma16(d[mt][g][0], d[mt][g][1], d[mt][g][2], d[mt][g][3],
                          a[mt][0], a[mt][1], a[mt][2], a[mt][3], b0, b1);
            }
        }
        __syncthreads();
        bool last = (t == Tc - 1);
#pragma unroll
        for (int mt = 0; mt < 4; ++mt)
#pragma unroll
        for (int rr = 0; rr < 2; ++rr) {
            float h2[2];
#pragma unroll
            for (int cc = 0; cc < 2; ++cc) {
                int di = rr*2 + cc;
                float iv = sig2 (d[mt][0][di]);
                float fv = sig2 (d[mt][1][di]);
                float gv = tanha(d[mt][2][di]);
                float ov = sig2 (d[mt][3][di]);
                int ci = mt*4 + rr*2 + cc;
                float cs = fv*cst[ci] + iv*gv;
                cst[ci] = cs;
                h2[cc] = ov*tanha(cs);
            }
            int edge = mt*16 + r0 + rr*8;
            AW[edge*WSTR + w*4 + c0] = pk(h2[0], h2[1]);
        }
        if (!last && tid < 64) {
            uint32_t* ar = AW + tid*WSTR;
            if (isEdge) {
                const float* xi = Xi + (t+1)*4;
                const float* xj = Xj + ((t+1)*64 + tid)*4;
                ar[32] = pk(xi[0], xi[1]);
                ar[33] = pk(xi[2], xj[0]);
                ar[34] = pk(xj[1], xj[2]);
            } else {
                const float* xj = Xj + ((t+1)*64 + tid)*4;
                ar[32] = pk(xj[0], xj[1]);
                ar[33] = pk(xj[2], 1.0f);
            }
        }
        __syncthreads();
    }

    // FC + sigmoid: warp w -> rows w*8..w*8+7 (h in bf16 words 0..31)
    const float* fW = isEdge ? cfW : (net ? gfW : bfW);
    const float* fb = isEdge ? cfb : (net ? gfb : bfb);
    if (lane < Pc) {
        float a[8];
#pragma unroll
        for (int e = 0; e < 8; ++e) a[e] = fb[lane];
        for (int wi = 0; wi < 32; ++wi) {
            float w0 = __ldg(&fW[lane*Hc + 2*wi]);
            float w1 = __ldg(&fW[lane*Hc + 2*wi + 1]);
#pragma unroll
            for (int e = 0; e < 8; ++e) {
                uint32_t hw = AW[(w*8 + e)*WSTR + wi];
                a[e] += w0*bflo(hw) + w1*bfhi(hw);
            }
        }
#pragma unroll
        for (int e = 0; e < 8; ++e) {
            float v = sigf(a[e]);
            int row = w*8 + e;
            if (isEdge) {
                g_clg[((size_t)((b*Nc + i)*Pc + lane))*Nc + (j0 + row)] = v;
            } else {
                int s = blk*64 + row;
                (net ? g_gamma : g_beta)[s*Pc + lane] = v;
            }
        }
    }
}

// ---------------- kernel 2: softmax over j + write epi + dense cs -------------
__global__ void softmax_kernel(float* __restrict__ out) {
    int row  = blockIdx.x*4 + (threadIdx.x >> 5);
    int lane = threadIdx.x & 31;
    const float* src = g_clg + (size_t)row*Nc;
    float v[4]; float s = 0.f;
#pragma unroll
    for (int q = 0; q < 4; ++q) { v[q] = __expf(src[lane + 32*q]); s += v[q]; }
#pragma unroll
    for (int off = 16; off; off >>= 1) s += __shfl_xor_sync(0xffffffffu, s, off);
    float inv = __fdividef(1.0f, s);
    int bi = row / Pc, p = row % Pc;
    int b = bi >> 7, i = bi & 127;
    float* e = out + 7168 + ((size_t)((b*Pc + p)*Nc + i))*130;
    float* cs = g_cs + ((size_t)((b*Pc + p)*Nc + i))*Nc;
    if (lane == 0) { e[0] = g_beta[row]; e[1] = g_gamma[row]; }
#pragma unroll
    for (int q = 0; q < 4; ++q) {
        float nv = v[q]*inv;
        e[2 + lane + 32*q]  = nv;
        cs[lane + 32*q]     = nv;
    }
}

// ---------------- kernel 3: SIR scan — direct L2 reads, register prefetch -----
__global__ void __launch_bounds__(512, 1)
sir_kernel(const float* __restrict__ x, float* __restrict__ out) {
    __shared__ float Ish[Nc];
    __shared__ float Bgs[2*1792];
    int b = blockIdx.x;
    int tid = threadIdx.x;
    int i = tid >> 2, q = tid & 3;

    for (int idx = tid; idx < 1792; idx += 512) {
        Bgs[idx]        = g_beta [b*1792 + idx];
        Bgs[1792 + idx] = g_gamma[b*1792 + idx];
    }
    float S = 0.f, I = 0.f, R = 0.f;
    if (q == 0) {
        const float* xp = x + (((size_t)(b*Tc + (Tc-1))*Nc) + i)*3;
        S = xp[0]; I = xp[1]; R = xp[2];
        Ish[i] = I;
    }
    __syncthreads();

    const float4* crow = (const float4*)(g_cs + ((size_t)b*Pc*Nc + i)*Nc) + q*8;
    float4 cur[8];
#pragma unroll
    for (int u = 0; u < 8; ++u) cur[u] = crow[u];

    for (int p = 0; p < Pc; ++p) {
        float4 nxt[8];
        if (p + 1 < Pc) {
            const float4* nr = crow + (size_t)(p+1)*(Nc*Nc/4);
#pragma unroll
            for (int u = 0; u < 8; ++u) nxt[u] = nr[u];
        }
        float acc = 0.f;
        const float* Iq = Ish + q*32;
#pragma unroll
        for (int u = 0; u < 8; ++u) {
            acc += cur[u].x*Iq[u*4+0];
            acc += cur[u].y*Iq[u*4+1];
            acc += cur[u].z*Iq[u*4+2];
            acc += cur[u].w*Iq[u*4+3];
        }
        acc += __shfl_xor_sync(0xffffffffu, acc, 1);
        acc += __shfl_xor_sync(0xffffffffu, acc, 2);
        __syncthreads();
        if (q == 0) {
            float beta = Bgs[i*Pc + p], gamma = Bgs[1792 + i*Pc + p];
            float Ntot = fmaxf(S + I + R, 1e-8f);
            float dS = -beta*S/Ntot*acc;
            float dI = -dS - gamma*I;
            float dR = gamma*I;
            float St = fmaxf(S + dS, 0.f);
            float It = fmaxf(I + dI, 0.f);
            float Rt = fmaxf(R + dR, 0.f);
            float sc = Ntot / fmaxf(St + It + Rt, 1e-8f);
            float Inew = fmaxf(-dS, 0.f);
            St *= sc; It *= sc; Rt *= sc;
            size_t idx = (size_t)(b*Pc + p)*Nc + i;
            out[idx] = It;                                      // o1
            float* o3 = out + 7168 + 931840 + idx*3;            // o3
            o3[0] = St; o3[1] = It; o3[2] = Rt;
            out[7168 + 931840 + 21504 + idx] = Inew;            // o4
            S = St; I = It; R = Rt;
            Ish[i] = I;
        }
        __syncthreads();
#pragma unroll
        for (int u = 0; u < 8; ++u) cur[u] = nxt[u];
    }
}

extern "C" void kernel_launch(void* const* d_in, const int* in_sizes, int n_in,
                              void* d_out, int out_size) {
    const float* x_s  = (const float*)d_in[0];
    const float* x    = (const float*)d_in[1];
    const float* bWih = (const float*)d_in[2];
    const float* bWhh = (const float*)d_in[3];
    const float* bb   = (const float*)d_in[4];
    const float* bfW  = (const float*)d_in[5];
    const float* bfb  = (const float*)d_in[6];
    const float* gWih = (const float*)d_in[7];
    const float* gWhh = (const float*)d_in[8];
    const float* gb   = (const float*)d_in[9];
    const float* gfW  = (const float*)d_in[10];
    const float* gfb  = (const float*)d_in[11];
    const float* cWih = (const float*)d_in[12];
    const float* cWhh = (const float*)d_in[13];
    const float* cb   = (const float*)d_in[14];
    const float* cfW  = (const float*)d_in[15];
    const float* cfb  = (const float*)d_in[16];
    float* out = (float*)d_out;

    static bool attr_done = false;
    if (!attr_done) {
        cudaFuncSetAttribute(lstm_mma_kernel, cudaFuncAttributeMaxDynamicSharedMemorySize, SMF_TOT*4);
        attr_done = true;
    }

    prep_wx_kernel<<<44, 256>>>(cWhh, cWih, cb, bWhh, bWih, bb, gWhh, gWih, gb);
    lstm_mma_kernel<<<1040, 256, SMF_TOT*4>>>(x_s, cfW, cfb, bfW, bfb, gfW, gfb);
    softmax_kernel<<<1792, 128>>>(out);
    sir_kernel<<<Bc, 512>>>(x, out);
}